// round 2
// baseline (speedup 1.0000x reference)
#include <cuda_runtime.h>
#include <cuda_bf16.h>
#include <math.h>

#define D 128
#define NMAX 100000

// Static scratch (no allocations allowed)
__device__ float g_agg1[(size_t)NMAX * D];   // 51.2 MB
__device__ float g_agg2[(size_t)NMAX * D];   // 51.2 MB
__device__ float g_h   [(size_t)NMAX * D];   // 51.2 MB
__device__ float g_jump[(size_t)NMAX * D];   // 51.2 MB
__device__ float g_deg [NMAX];
__device__ float g_inv [NMAX];

__device__ __forceinline__ void red_add_v4(float* p, float4 v) {
    asm volatile("red.global.add.v4.f32 [%0], {%1,%2,%3,%4};"
                 :: "l"(p), "f"(v.x), "f"(v.y), "f"(v.z), "f"(v.w) : "memory");
}

__device__ __forceinline__ float tanh_approx(float x) {
    float y;
    asm("tanh.approx.f32 %0, %1;" : "=f"(y) : "f"(x));
    return y;
}

// ---------------------------------------------------------------------------
// Degree precount (shared by both conv layers) + inverse
// ---------------------------------------------------------------------------
__global__ void deg_count(const int* __restrict__ ei, int E) {
    int i = blockIdx.x * blockDim.x + threadIdx.x;
    if (i < E) atomicAdd(&g_deg[__ldg(ei + E + i)], 1.0f);
}

__global__ void inv_deg_k(int Nn) {
    int i = blockIdx.x * blockDim.x + threadIdx.x;
    if (i < Nn) g_inv[i] = 1.0f / fmaxf(g_deg[i], 1.0f);
}

// ---------------------------------------------------------------------------
// Conv scatter: one warp per edge.  agg[dst] += x[src] * rel[type]
// ---------------------------------------------------------------------------
__global__ __launch_bounds__(256)
void conv_scatter(const float* __restrict__ x,
                  const float* __restrict__ rel,
                  const int* __restrict__ ei,   // [2, E] flattened
                  const int* __restrict__ et,
                  float* __restrict__ agg,
                  int E)
{
    int lane = threadIdx.x & 31;
    int warp = blockIdx.x * (blockDim.x >> 5) + (threadIdx.x >> 5);
    int nwarps = gridDim.x * (blockDim.x >> 5);
    for (int e = warp; e < E; e += nwarps) {
        int src = __ldg(ei + e);
        int dst = __ldg(ei + E + e);
        int t   = __ldg(et + e);
        float4 xv = reinterpret_cast<const float4*>(x   + (size_t)src * D)[lane];
        float4 rv = reinterpret_cast<const float4*>(rel + (size_t)t   * D)[lane];
        float4 m = make_float4(xv.x * rv.x, xv.y * rv.y, xv.z * rv.z, xv.w * rv.w);
        red_add_v4(agg + (size_t)dst * D + lane * 4, m);
    }
}

// ---------------------------------------------------------------------------
// Jump scatter (into private buffer; consumed by gemm2 epilogue)
// ---------------------------------------------------------------------------
__global__ __launch_bounds__(256)
void jump_scatter(const float* __restrict__ emb,
                  const float* __restrict__ ew,
                  const float* __restrict__ jwp,
                  const int* __restrict__ ej,
                  float* __restrict__ out, int EJ)
{
    float jw = __ldg(jwp);
    int lane = threadIdx.x & 31;
    int warp = blockIdx.x * (blockDim.x >> 5) + (threadIdx.x >> 5);
    int nwarps = gridDim.x * (blockDim.x >> 5);
    for (int e = warp; e < EJ; e += nwarps) {
        int src = __ldg(ej + e);
        int dst = __ldg(ej + EJ + e);
        float w = jw * __ldg(ew + e);
        float4 v = reinterpret_cast<const float4*>(emb + (size_t)src * D)[lane];
        v.x *= w; v.y *= w; v.z *= w; v.w *= w;
        red_add_v4(out + (size_t)dst * D + lane * 4, v);
    }
}

// ---------------------------------------------------------------------------
// Fused GEMM + epilogue:
//   out = x + res * tanh( (agg*inv_deg) @ Wa + x @ Wx ) [+ jump]
// A = [agg_norm | x] (N x 256),  B = [[Wa],[Wx]] (256 x 128)
// bf16 hi/lo split, 3 passes (AhBh + AlBh + AhBl) -> ~fp32 accuracy.
// ---------------------------------------------------------------------------
#define BM 64
#define KK (2 * D)          // 256
#define AS (KK + 8)         // 264
#define BS (D + 8)          // 136
#define SMEM_BYTES ((2 * BM * AS + 2 * KK * BS) * 2)   // 206848

__global__ __launch_bounds__(256, 1)
void fused_gemm(const float* __restrict__ x,
                const float* __restrict__ Wa,
                const float* __restrict__ Wx,
                const float* __restrict__ resp,
                const float* __restrict__ agg,
                const float* __restrict__ jadd,   // nullable
                float* __restrict__ out,
                int Nn, int ntiles)
{
    extern __shared__ __nv_bfloat16 sm[];
    __nv_bfloat16* Ah = sm;
    __nv_bfloat16* Al = Ah + BM * AS;
    __nv_bfloat16* Bh = Al + BM * AS;
    __nv_bfloat16* Bl = Bh + KK * BS;

    int tid  = threadIdx.x;
    int lane = tid & 31;
    int wid  = tid >> 5;
    int wm   = wid & 3;     // m-tile (16 rows)
    int wn   = wid >> 2;    // n-half (64 cols)

    // ---- stage weights once per block, hi/lo bf16, packed 8B stores ----
    for (int idx = tid; idx < KK * D / 4; idx += 256) {
        int k  = idx >> 5;             // 0..255
        int c4 = (idx & 31) * 4;
        const float* src = (k < D) ? (Wa + (size_t)k * D) : (Wx + (size_t)(k - D) * D);
        float4 v = *reinterpret_cast<const float4*>(src + c4);
        __nv_bfloat162 h01 = __floats2bfloat162_rn(v.x, v.y);
        __nv_bfloat162 h23 = __floats2bfloat162_rn(v.z, v.w);
        float2 f01 = __bfloat1622float2(h01);
        float2 f23 = __bfloat1622float2(h23);
        __nv_bfloat162 l01 = __floats2bfloat162_rn(v.x - f01.x, v.y - f01.y);
        __nv_bfloat162 l23 = __floats2bfloat162_rn(v.z - f23.x, v.w - f23.y);
        *reinterpret_cast<__nv_bfloat162*>(&Bh[k * BS + c4])     = h01;
        *reinterpret_cast<__nv_bfloat162*>(&Bh[k * BS + c4 + 2]) = h23;
        *reinterpret_cast<__nv_bfloat162*>(&Bl[k * BS + c4])     = l01;
        *reinterpret_cast<__nv_bfloat162*>(&Bl[k * BS + c4 + 2]) = l23;
    }

    float resv = __ldg(resp);

    for (int tile = blockIdx.x; tile < ntiles; tile += gridDim.x) {
        int row0 = tile * BM;
        __syncthreads();   // smem reuse guard (covers B staging on iter 0)

        // ---- stage A tile: [agg*inv | x], hi/lo bf16, packed stores ----
        for (int idx = tid; idx < BM * KK / 4; idx += 256) {
            int r  = idx >> 6;             // 0..63
            int c4 = (idx & 63) * 4;       // 0..252
            int row = row0 + r;
            float4 v = make_float4(0.f, 0.f, 0.f, 0.f);
            if (row < Nn) {
                if (c4 < D) {
                    v = *reinterpret_cast<const float4*>(agg + (size_t)row * D + c4);
                    float id = __ldg(&g_inv[row]);
                    v.x *= id; v.y *= id; v.z *= id; v.w *= id;
                } else {
                    v = *reinterpret_cast<const float4*>(x + (size_t)row * D + (c4 - D));
                }
            }
            __nv_bfloat162 h01 = __floats2bfloat162_rn(v.x, v.y);
            __nv_bfloat162 h23 = __floats2bfloat162_rn(v.z, v.w);
            float2 f01 = __bfloat1622float2(h01);
            float2 f23 = __bfloat1622float2(h23);
            __nv_bfloat162 l01 = __floats2bfloat162_rn(v.x - f01.x, v.y - f01.y);
            __nv_bfloat162 l23 = __floats2bfloat162_rn(v.z - f23.x, v.w - f23.y);
            *reinterpret_cast<__nv_bfloat162*>(&Ah[r * AS + c4])     = h01;
            *reinterpret_cast<__nv_bfloat162*>(&Ah[r * AS + c4 + 2]) = h23;
            *reinterpret_cast<__nv_bfloat162*>(&Al[r * AS + c4])     = l01;
            *reinterpret_cast<__nv_bfloat162*>(&Al[r * AS + c4 + 2]) = l23;
        }
        __syncthreads();

        float acc[8][4];
        #pragma unroll
        for (int j = 0; j < 8; j++)
            #pragma unroll
            for (int q = 0; q < 4; q++) acc[j][q] = 0.f;

        int arow = wm * 16 + (lane & 7) + ((lane >> 3) & 1) * 8;
        int acol = ((lane >> 4) & 1) * 8;
        int brow = (lane & 7) + ((lane >> 3) & 1) * 8;
        int bcol = wn * 64 + ((lane >> 4) & 1) * 8;

        #pragma unroll
        for (int pass = 0; pass < 3; pass++) {
            const __nv_bfloat16* As = (pass == 1) ? Al : Ah;
            const __nv_bfloat16* Bs = (pass == 2) ? Bl : Bh;
            #pragma unroll
            for (int kk = 0; kk < KK; kk += 16) {
                unsigned a0, a1, a2, a3;
                {
                    unsigned ad = (unsigned)__cvta_generic_to_shared(
                        &As[(size_t)arow * AS + kk + acol]);
                    asm volatile(
                        "ldmatrix.sync.aligned.m8n8.x4.shared.b16 {%0,%1,%2,%3}, [%4];"
                        : "=r"(a0), "=r"(a1), "=r"(a2), "=r"(a3) : "r"(ad));
                }
                #pragma unroll
                for (int nt = 0; nt < 4; nt++) {
                    unsigned b0, b1, b2, b3;
                    unsigned bd = (unsigned)__cvta_generic_to_shared(
                        &Bs[(size_t)(kk + brow) * BS + bcol + nt * 16]);
                    asm volatile(
                        "ldmatrix.sync.aligned.m8n8.x4.trans.shared.b16 {%0,%1,%2,%3}, [%4];"
                        : "=r"(b0), "=r"(b1), "=r"(b2), "=r"(b3) : "r"(bd));
                    asm volatile(
                        "mma.sync.aligned.m16n8k16.row.col.f32.bf16.bf16.f32 "
                        "{%0,%1,%2,%3}, {%4,%5,%6,%7}, {%8,%9}, {%0,%1,%2,%3};"
                        : "+f"(acc[nt*2][0]), "+f"(acc[nt*2][1]),
                          "+f"(acc[nt*2][2]), "+f"(acc[nt*2][3])
                        : "r"(a0), "r"(a1), "r"(a2), "r"(a3), "r"(b0), "r"(b1));
                    asm volatile(
                        "mma.sync.aligned.m16n8k16.row.col.f32.bf16.bf16.f32 "
                        "{%0,%1,%2,%3}, {%4,%5,%6,%7}, {%8,%9}, {%0,%1,%2,%3};"
                        : "+f"(acc[nt*2+1][0]), "+f"(acc[nt*2+1][1]),
                          "+f"(acc[nt*2+1][2]), "+f"(acc[nt*2+1][3])
                        : "r"(a0), "r"(a1), "r"(a2), "r"(a3), "r"(b2), "r"(b3));
                }
            }
        }

        // ---- epilogue: out = x + res * tanh(acc) [+ jump] ----
        int g = lane >> 2;
        int cbase = wn * 64 + (lane & 3) * 2;
        int r0 = row0 + wm * 16 + g;
        int r1 = r0 + 8;
        #pragma unroll
        for (int j = 0; j < 8; j++) {
            int col = cbase + j * 8;
            if (r0 < Nn) {
                float2 xv = *reinterpret_cast<const float2*>(x + (size_t)r0 * D + col);
                float2 o;
                o.x = xv.x + resv * tanh_approx(acc[j][0]);
                o.y = xv.y + resv * tanh_approx(acc[j][1]);
                if (jadd) {
                    float2 jv = *reinterpret_cast<const float2*>(jadd + (size_t)r0 * D + col);
                    o.x += jv.x; o.y += jv.y;
                }
                *reinterpret_cast<float2*>(out + (size_t)r0 * D + col) = o;
            }
            if (r1 < Nn) {
                float2 xv = *reinterpret_cast<const float2*>(x + (size_t)r1 * D + col);
                float2 o;
                o.x = xv.x + resv * tanh_approx(acc[j][2]);
                o.y = xv.y + resv * tanh_approx(acc[j][3]);
                if (jadd) {
                    float2 jv = *reinterpret_cast<const float2*>(jadd + (size_t)r1 * D + col);
                    o.x += jv.x; o.y += jv.y;
                }
                *reinterpret_cast<float2*>(out + (size_t)r1 * D + col) = o;
            }
        }
    }
}

// ---------------------------------------------------------------------------
extern "C" void kernel_launch(void* const* d_in, const int* in_sizes, int n_in,
                              void* d_out, int out_size)
{
    const float* emb    = (const float*)d_in[0];
    const float* change = (const float*)d_in[1];
    const float* W1     = (const float*)d_in[2];
    const float* Wl1    = (const float*)d_in[3];
    const float* rel1   = (const float*)d_in[4];
    const float* W2     = (const float*)d_in[5];
    const float* Wl2    = (const float*)d_in[6];
    const float* rel2   = (const float*)d_in[7];
    const float* res    = (const float*)d_in[8];
    const float* jw     = (const float*)d_in[9];
    const float* ewj    = (const float*)d_in[10];
    const int*   ei     = (const int*)d_in[11];
    const int*   et     = (const int*)d_in[12];
    const int*   ej     = (const int*)d_in[13];

    int Nn = in_sizes[0] / D;
    int E  = in_sizes[12];
    int EJ = in_sizes[10];
    int ntiles = (Nn + BM - 1) / BM;
    size_t rowBytes = (size_t)Nn * D * sizeof(float);

    float* out_change = (float*)d_out;
    float* out_dch    = (float*)d_out + (size_t)Nn * D;

    void *p_agg1, *p_agg2, *p_h, *p_jump, *p_deg;
    cudaGetSymbolAddress(&p_agg1, g_agg1);
    cudaGetSymbolAddress(&p_agg2, g_agg2);
    cudaGetSymbolAddress(&p_h,    g_h);
    cudaGetSymbolAddress(&p_jump, g_jump);
    cudaGetSymbolAddress(&p_deg,  g_deg);
    float* agg1 = (float*)p_agg1;
    float* agg2 = (float*)p_agg2;
    float* hbuf = (float*)p_h;
    float* jbuf = (float*)p_jump;

    cudaFuncSetAttribute(fused_gemm, cudaFuncAttributeMaxDynamicSharedMemorySize,
                         SMEM_BYTES);

    // Forked streams for off-critical-path work (created per call; host-side
    // objects only, graph captures the dependency structure).
    cudaStream_t s1, s2;
    cudaStreamCreateWithFlags(&s1, cudaStreamNonBlocking);
    cudaStreamCreateWithFlags(&s2, cudaStreamNonBlocking);
    cudaEvent_t eFork, eD, eJ, eZ2, eC;
    cudaEventCreateWithFlags(&eFork, cudaEventDisableTiming);
    cudaEventCreateWithFlags(&eD,    cudaEventDisableTiming);
    cudaEventCreateWithFlags(&eJ,    cudaEventDisableTiming);
    cudaEventCreateWithFlags(&eZ2,   cudaEventDisableTiming);
    cudaEventCreateWithFlags(&eC,    cudaEventDisableTiming);

    cudaEventRecord(eFork, 0);

    // --- s1: degree precount, then jump diffusion (both off critical path) ---
    cudaStreamWaitEvent(s1, eFork, 0);
    cudaMemsetAsync(p_deg, 0, (size_t)Nn * sizeof(float), s1);
    deg_count<<<(E + 255) / 256, 256, 0, s1>>>(ei, E);
    inv_deg_k<<<(Nn + 255) / 256, 256, 0, s1>>>(Nn);
    cudaEventRecord(eD, s1);
    cudaMemsetAsync(p_jump, 0, rowBytes, s1);
    jump_scatter<<<2368, 256, 0, s1>>>(emb, ewj, jw, ej, jbuf, EJ);
    cudaEventRecord(eJ, s1);

    // --- s2: layer-2 agg zero + change passthrough ---
    cudaStreamWaitEvent(s2, eFork, 0);
    cudaMemsetAsync(p_agg2, 0, rowBytes, s2);
    cudaEventRecord(eZ2, s2);
    cudaMemcpyAsync(out_change, change, rowBytes, cudaMemcpyDeviceToDevice, s2);
    cudaEventRecord(eC, s2);

    // --- s0 (capture stream): the critical spine ---
    cudaMemsetAsync(p_agg1, 0, rowBytes, 0);
    conv_scatter<<<4736, 256>>>(emb, rel1, ei, et, agg1, E);
    cudaStreamWaitEvent(0, eD, 0);
    fused_gemm<<<152, 256, SMEM_BYTES>>>(emb, W1, Wl1, res, agg1, nullptr,
                                         hbuf, Nn, ntiles);
    cudaStreamWaitEvent(0, eZ2, 0);
    conv_scatter<<<4736, 256>>>(hbuf, rel2, ei, et, agg2, E);
    cudaStreamWaitEvent(0, eJ, 0);
    fused_gemm<<<152, 256, SMEM_BYTES>>>(hbuf, W2, Wl2, res, agg2, jbuf,
                                         out_dch, Nn, ntiles);
    cudaStreamWaitEvent(0, eC, 0);

    // Join complete on stream 0; destroy host-side handles.
    cudaEventDestroy(eFork); cudaEventDestroy(eD); cudaEventDestroy(eJ);
    cudaEventDestroy(eZ2);   cudaEventDestroy(eC);
    cudaStreamDestroy(s1);   cudaStreamDestroy(s2);
}

// round 3
// speedup vs baseline: 1.7619x; 1.7619x over previous
#include <cuda_runtime.h>
#include <cuda_bf16.h>
#include <math.h>

#define D 128
#define NMAX 100000

// Static scratch (no allocations allowed)
__device__ float g_agg1[(size_t)NMAX * D];   // 51.2 MB
__device__ float g_agg2[(size_t)NMAX * D];   // 51.2 MB
__device__ float g_h   [(size_t)NMAX * D];   // 51.2 MB
__device__ float g_deg [NMAX];
__device__ float g_inv [NMAX];

__device__ __forceinline__ void red_add_v4(float* p, float4 v) {
    asm volatile("red.global.add.v4.f32 [%0], {%1,%2,%3,%4};"
                 :: "l"(p), "f"(v.x), "f"(v.y), "f"(v.z), "f"(v.w) : "memory");
}

__device__ __forceinline__ float tanh_approx(float x) {
    float y;
    asm("tanh.approx.f32 %0, %1;" : "=f"(y) : "f"(x));
    return y;
}

// ---------------------------------------------------------------------------
// Degree precount (shared by both conv layers) + inverse
// ---------------------------------------------------------------------------
__global__ void deg_count(const int* __restrict__ ei, int E) {
    int i = blockIdx.x * blockDim.x + threadIdx.x;
    if (i < E) atomicAdd(&g_deg[__ldg(ei + E + i)], 1.0f);
}

__global__ void inv_deg_k(int Nn) {
    int i = blockIdx.x * blockDim.x + threadIdx.x;
    if (i < Nn) g_inv[i] = 1.0f / fmaxf(g_deg[i], 1.0f);
}

// ---------------------------------------------------------------------------
// Conv scatter: one warp per edge.  agg[dst] += x[src] * rel[type]
// ---------------------------------------------------------------------------
__global__ __launch_bounds__(256)
void conv_scatter(const float* __restrict__ x,
                  const float* __restrict__ rel,
                  const int* __restrict__ ei,   // [2, E] flattened
                  const int* __restrict__ et,
                  float* __restrict__ agg,
                  int E)
{
    int lane = threadIdx.x & 31;
    int warp = blockIdx.x * (blockDim.x >> 5) + (threadIdx.x >> 5);
    int nwarps = gridDim.x * (blockDim.x >> 5);
    for (int e = warp; e < E; e += nwarps) {
        int src = __ldg(ei + e);
        int dst = __ldg(ei + E + e);
        int t   = __ldg(et + e);
        float4 xv = reinterpret_cast<const float4*>(x   + (size_t)src * D)[lane];
        float4 rv = reinterpret_cast<const float4*>(rel + (size_t)t   * D)[lane];
        float4 m = make_float4(xv.x * rv.x, xv.y * rv.y, xv.z * rv.z, xv.w * rv.w);
        red_add_v4(agg + (size_t)dst * D + lane * 4, m);
    }
}

// ---------------------------------------------------------------------------
// Jump scatter: out[dst] += jw * ew[e] * emb[src]  (accumulates onto out_dch)
// ---------------------------------------------------------------------------
__global__ __launch_bounds__(256)
void jump_scatter(const float* __restrict__ emb,
                  const float* __restrict__ ew,
                  const float* __restrict__ jwp,
                  const int* __restrict__ ej,
                  float* __restrict__ out, int EJ)
{
    float jw = __ldg(jwp);
    int lane = threadIdx.x & 31;
    int warp = blockIdx.x * (blockDim.x >> 5) + (threadIdx.x >> 5);
    int nwarps = gridDim.x * (blockDim.x >> 5);
    for (int e = warp; e < EJ; e += nwarps) {
        int src = __ldg(ej + e);
        int dst = __ldg(ej + EJ + e);
        float w = jw * __ldg(ew + e);
        float4 v = reinterpret_cast<const float4*>(emb + (size_t)src * D)[lane];
        v.x *= w; v.y *= w; v.z *= w; v.w *= w;
        red_add_v4(out + (size_t)dst * D + lane * 4, v);
    }
}

// ---------------------------------------------------------------------------
// Fused GEMM + epilogue:  out = x + res * tanh( (agg*inv) @ Wa + x @ Wx )
// A = [agg_norm | x] (N x 256), B = [[Wa],[Wx]] (256 x 128), single-pass bf16.
// Block = 64 rows x 128 cols, 8 warps (4 m-tiles x 2 n-halves).
// smem ~101KB -> 2 CTAs/SM.
// ---------------------------------------------------------------------------
#define BM 64
#define KK (2 * D)          // 256
#define AS (KK + 8)         // 264
#define BS (D + 8)          // 136
#define SMEM_BYTES ((BM * AS + KK * BS) * 2)   // 103424

__global__ __launch_bounds__(256, 2)
void fused_gemm(const float* __restrict__ x,
                const float* __restrict__ Wa,
                const float* __restrict__ Wx,
                const float* __restrict__ resp,
                const float* __restrict__ agg,
                float* __restrict__ out,
                int Nn, int ntiles)
{
    extern __shared__ __nv_bfloat16 sm[];
    __nv_bfloat16* Ah = sm;
    __nv_bfloat16* Bh = Ah + BM * AS;

    int tid  = threadIdx.x;
    int lane = tid & 31;
    int wid  = tid >> 5;
    int wm   = wid & 3;     // m-tile (16 rows)
    int wn   = wid >> 2;    // n-half (64 cols)

    // ---- stage weights once per block ----
    for (int idx = tid; idx < KK * D / 4; idx += 256) {
        int k  = idx >> 5;             // 0..255
        int c4 = (idx & 31) * 4;
        const float* src = (k < D) ? (Wa + (size_t)k * D) : (Wx + (size_t)(k - D) * D);
        float4 v = *reinterpret_cast<const float4*>(src + c4);
        *reinterpret_cast<__nv_bfloat162*>(&Bh[k * BS + c4])     = __floats2bfloat162_rn(v.x, v.y);
        *reinterpret_cast<__nv_bfloat162*>(&Bh[k * BS + c4 + 2]) = __floats2bfloat162_rn(v.z, v.w);
    }

    float resv = __ldg(resp);

    for (int tile = blockIdx.x; tile < ntiles; tile += gridDim.x) {
        int row0 = tile * BM;
        __syncthreads();   // smem reuse guard (covers B staging on iter 0)

        // ---- stage A tile: [agg*inv | x] ----
        for (int idx = tid; idx < BM * KK / 4; idx += 256) {
            int r  = idx >> 6;             // 0..63
            int c4 = (idx & 63) * 4;       // 0..252
            int row = row0 + r;
            float4 v = make_float4(0.f, 0.f, 0.f, 0.f);
            if (row < Nn) {
                if (c4 < D) {
                    v = *reinterpret_cast<const float4*>(agg + (size_t)row * D + c4);
                    float id = __ldg(&g_inv[row]);
                    v.x *= id; v.y *= id; v.z *= id; v.w *= id;
                } else {
                    v = *reinterpret_cast<const float4*>(x + (size_t)row * D + (c4 - D));
                }
            }
            *reinterpret_cast<__nv_bfloat162*>(&Ah[r * AS + c4])     = __floats2bfloat162_rn(v.x, v.y);
            *reinterpret_cast<__nv_bfloat162*>(&Ah[r * AS + c4 + 2]) = __floats2bfloat162_rn(v.z, v.w);
        }
        __syncthreads();

        float acc[8][4];
        #pragma unroll
        for (int j = 0; j < 8; j++)
            #pragma unroll
            for (int q = 0; q < 4; q++) acc[j][q] = 0.f;

        int arow = wm * 16 + (lane & 7) + ((lane >> 3) & 1) * 8;
        int acol = ((lane >> 4) & 1) * 8;
        int brow = (lane & 7) + ((lane >> 3) & 1) * 8;
        int bcol = wn * 64 + ((lane >> 4) & 1) * 8;

        #pragma unroll
        for (int kk = 0; kk < KK; kk += 16) {
            unsigned a0, a1, a2, a3;
            {
                unsigned ad = (unsigned)__cvta_generic_to_shared(
                    &Ah[(size_t)arow * AS + kk + acol]);
                asm volatile(
                    "ldmatrix.sync.aligned.m8n8.x4.shared.b16 {%0,%1,%2,%3}, [%4];"
                    : "=r"(a0), "=r"(a1), "=r"(a2), "=r"(a3) : "r"(ad));
            }
            #pragma unroll
            for (int nt = 0; nt < 4; nt++) {
                unsigned b0, b1, b2, b3;
                unsigned bd = (unsigned)__cvta_generic_to_shared(
                    &Bh[(size_t)(kk + brow) * BS + bcol + nt * 16]);
                asm volatile(
                    "ldmatrix.sync.aligned.m8n8.x4.trans.shared.b16 {%0,%1,%2,%3}, [%4];"
                    : "=r"(b0), "=r"(b1), "=r"(b2), "=r"(b3) : "r"(bd));
                asm volatile(
                    "mma.sync.aligned.m16n8k16.row.col.f32.bf16.bf16.f32 "
                    "{%0,%1,%2,%3}, {%4,%5,%6,%7}, {%8,%9}, {%0,%1,%2,%3};"
                    : "+f"(acc[nt*2][0]), "+f"(acc[nt*2][1]),
                      "+f"(acc[nt*2][2]), "+f"(acc[nt*2][3])
                    : "r"(a0), "r"(a1), "r"(a2), "r"(a3), "r"(b0), "r"(b1));
                asm volatile(
                    "mma.sync.aligned.m16n8k16.row.col.f32.bf16.bf16.f32 "
                    "{%0,%1,%2,%3}, {%4,%5,%6,%7}, {%8,%9}, {%0,%1,%2,%3};"
                    : "+f"(acc[nt*2+1][0]), "+f"(acc[nt*2+1][1]),
                      "+f"(acc[nt*2+1][2]), "+f"(acc[nt*2+1][3])
                    : "r"(a0), "r"(a1), "r"(a2), "r"(a3), "r"(b2), "r"(b3));
            }
        }

        // ---- epilogue: out = x + res * tanh(acc) ----
        int g = lane >> 2;
        int cbase = wn * 64 + (lane & 3) * 2;
        int r0 = row0 + wm * 16 + g;
        int r1 = r0 + 8;
        #pragma unroll
        for (int j = 0; j < 8; j++) {
            int col = cbase + j * 8;
            if (r0 < Nn) {
                float2 xv = *reinterpret_cast<const float2*>(x + (size_t)r0 * D + col);
                float2 o;
                o.x = xv.x + resv * tanh_approx(acc[j][0]);
                o.y = xv.y + resv * tanh_approx(acc[j][1]);
                *reinterpret_cast<float2*>(out + (size_t)r0 * D + col) = o;
            }
            if (r1 < Nn) {
                float2 xv = *reinterpret_cast<const float2*>(x + (size_t)r1 * D + col);
                float2 o;
                o.x = xv.x + resv * tanh_approx(acc[j][2]);
                o.y = xv.y + resv * tanh_approx(acc[j][3]);
                *reinterpret_cast<float2*>(out + (size_t)r1 * D + col) = o;
            }
        }
    }
}

// ---------------------------------------------------------------------------
extern "C" void kernel_launch(void* const* d_in, const int* in_sizes, int n_in,
                              void* d_out, int out_size)
{
    const float* emb    = (const float*)d_in[0];
    const float* change = (const float*)d_in[1];
    const float* W1     = (const float*)d_in[2];
    const float* Wl1    = (const float*)d_in[3];
    const float* rel1   = (const float*)d_in[4];
    const float* W2     = (const float*)d_in[5];
    const float* Wl2    = (const float*)d_in[6];
    const float* rel2   = (const float*)d_in[7];
    const float* res    = (const float*)d_in[8];
    const float* jw     = (const float*)d_in[9];
    const float* ewj    = (const float*)d_in[10];
    const int*   ei     = (const int*)d_in[11];
    const int*   et     = (const int*)d_in[12];
    const int*   ej     = (const int*)d_in[13];

    int Nn = in_sizes[0] / D;
    int E  = in_sizes[12];
    int EJ = in_sizes[10];
    int ntiles = (Nn + BM - 1) / BM;
    size_t rowBytes = (size_t)Nn * D * sizeof(float);

    float* out_change = (float*)d_out;
    float* out_dch    = (float*)d_out + (size_t)Nn * D;

    void *p_agg1, *p_agg2, *p_h, *p_deg;
    cudaGetSymbolAddress(&p_agg1, g_agg1);
    cudaGetSymbolAddress(&p_agg2, g_agg2);
    cudaGetSymbolAddress(&p_h,    g_h);
    cudaGetSymbolAddress(&p_deg,  g_deg);
    float* agg1 = (float*)p_agg1;
    float* agg2 = (float*)p_agg2;
    float* hbuf = (float*)p_h;

    cudaFuncSetAttribute(fused_gemm, cudaFuncAttributeMaxDynamicSharedMemorySize,
                         SMEM_BYTES);

    // Serial spine on stream 0 — every phase is bandwidth-bound, so minimize
    // total bytes; no stream forking (R2 showed it only adds traffic).
    cudaMemsetAsync(p_deg,  0, (size_t)Nn * sizeof(float), 0);
    cudaMemsetAsync(p_agg1, 0, rowBytes, 0);
    deg_count<<<(E + 255) / 256, 256>>>(ei, E);
    inv_deg_k<<<(Nn + 255) / 256, 256>>>(Nn);

    // Layer 1
    conv_scatter<<<4736, 256>>>(emb, rel1, ei, et, agg1, E);
    fused_gemm<<<304, 256, SMEM_BYTES>>>(emb, W1, Wl1, res, agg1, hbuf, Nn, ntiles);

    // Layer 2
    cudaMemsetAsync(p_agg2, 0, rowBytes, 0);
    conv_scatter<<<4736, 256>>>(hbuf, rel2, ei, et, agg2, E);
    fused_gemm<<<304, 256, SMEM_BYTES>>>(hbuf, W2, Wl2, res, agg2, out_dch, Nn, ntiles);

    // Jump diffusion accumulates directly onto dchange
    jump_scatter<<<2368, 256>>>(emb, ewj, jw, ej, out_dch, EJ);

    // change passthrough
    cudaMemcpyAsync(out_change, change, rowBytes, cudaMemcpyDeviceToDevice, 0);
}

// round 5
// speedup vs baseline: 1.9526x; 1.1082x over previous
#include <cuda_runtime.h>
#include <cuda_bf16.h>
#include <math.h>

#define D 128
#define NMAX 100000

// Static scratch (no allocations allowed)
__device__ float g_agg1[(size_t)NMAX * D];
__device__ float g_agg2[(size_t)NMAX * D];
__device__ float g_h   [(size_t)NMAX * D];
__device__ float g_deg [NMAX];
__device__ float g_inv [NMAX];

__device__ __forceinline__ void red_add_v4(float* p, float4 v) {
    asm volatile("red.global.add.v4.f32 [%0], {%1,%2,%3,%4};"
                 :: "l"(p), "f"(v.x), "f"(v.y), "f"(v.z), "f"(v.w) : "memory");
}

__device__ __forceinline__ float tanh_approx(float x) {
    float y;
    asm("tanh.approx.f32 %0, %1;" : "=f"(y) : "f"(x));
    return y;
}

__device__ __forceinline__ void cp16(unsigned saddr, const void* g, int srcsize) {
    asm volatile("cp.async.cg.shared.global [%0], [%1], 16, %2;"
                 :: "r"(saddr), "l"(g), "r"(srcsize));
}

// ---------------------------------------------------------------------------
// Degree precount + inverse
// ---------------------------------------------------------------------------
__global__ void deg_count(const int* __restrict__ ei, int E) {
    int i = blockIdx.x * blockDim.x + threadIdx.x;
    if (i < E) atomicAdd(&g_deg[__ldg(ei + E + i)], 1.0f);
}

__global__ void inv_deg_k(int Nn) {
    int i = blockIdx.x * blockDim.x + threadIdx.x;
    if (i < Nn) g_inv[i] = 1.0f / fmaxf(g_deg[i], 1.0f);
}

// ---------------------------------------------------------------------------
// Conv scatter: one warp per edge.  agg[dst] += x[src] * rel[type]
// ---------------------------------------------------------------------------
__global__ __launch_bounds__(256)
void conv_scatter(const float* __restrict__ x,
                  const float* __restrict__ rel,
                  const int* __restrict__ ei,
                  const int* __restrict__ et,
                  float* __restrict__ agg,
                  int E)
{
    int lane = threadIdx.x & 31;
    int warp = blockIdx.x * (blockDim.x >> 5) + (threadIdx.x >> 5);
    int nwarps = gridDim.x * (blockDim.x >> 5);
    for (int e = warp; e < E; e += nwarps) {
        int src = __ldg(ei + e);
        int dst = __ldg(ei + E + e);
        int t   = __ldg(et + e);
        float4 xv = reinterpret_cast<const float4*>(x   + (size_t)src * D)[lane];
        float4 rv = reinterpret_cast<const float4*>(rel + (size_t)t   * D)[lane];
        float4 m = make_float4(xv.x * rv.x, xv.y * rv.y, xv.z * rv.z, xv.w * rv.w);
        red_add_v4(agg + (size_t)dst * D + lane * 4, m);
    }
}

// ---------------------------------------------------------------------------
// Jump scatter: out[dst] += jw * ew[e] * emb[src]
// ---------------------------------------------------------------------------
__global__ __launch_bounds__(256)
void jump_scatter(const float* __restrict__ emb,
                  const float* __restrict__ ew,
                  const float* __restrict__ jwp,
                  const int* __restrict__ ej,
                  float* __restrict__ out, int EJ)
{
    float jw = __ldg(jwp);
    int lane = threadIdx.x & 31;
    int warp = blockIdx.x * (blockDim.x >> 5) + (threadIdx.x >> 5);
    int nwarps = gridDim.x * (blockDim.x >> 5);
    for (int e = warp; e < EJ; e += nwarps) {
        int src = __ldg(ej + e);
        int dst = __ldg(ej + EJ + e);
        float w = jw * __ldg(ew + e);
        float4 v = reinterpret_cast<const float4*>(emb + (size_t)src * D)[lane];
        v.x *= w; v.y *= w; v.z *= w; v.w *= w;
        red_add_v4(out + (size_t)dst * D + lane * 4, v);
    }
}

// ---------------------------------------------------------------------------
// Pipelined fused GEMM:  out = x + res * tanh( (agg*inv) @ Wa + x @ Wx )
// A = [agg | x] (N x 256) staged RAW fp32 via cp.async, double-buffered.
// bf16 conversion (+ deg scaling) happens in the fragment build (LDS.64+cvt).
// Epilogue reads x from smem fp32 (no global re-read).
// 512 threads = 16 warps (4 m-tiles x 4 n-quarters), 1 CTA/SM.
// ---------------------------------------------------------------------------
#define BM 64
#define KK 256
#define ASF 260                              // fp32 per A row (pad: bank spread)
#define BS  136                              // bf16 per B row
#define SMEM_A_BYTES (2 * BM * ASF * 4)      // 133120
#define SMEM_B_BYTES (KK * BS * 2)           // 69632
#define SMEM_BYTES   (SMEM_A_BYTES + SMEM_B_BYTES)   // 202752

__global__ __launch_bounds__(512, 1)
void fused_gemm(const float* __restrict__ x,
                const float* __restrict__ Wa,
                const float* __restrict__ Wx,
                const float* __restrict__ resp,
                const float* __restrict__ agg,
                float* __restrict__ out,
                int Nn, int ntiles)
{
    extern __shared__ char smraw[];
    float* Asm = reinterpret_cast<float*>(smraw);                    // [2][BM*ASF]
    __nv_bfloat16* Bs = reinterpret_cast<__nv_bfloat16*>(smraw + SMEM_A_BYTES);

    int tid  = threadIdx.x;
    int lane = tid & 31;
    int wid  = tid >> 5;
    int wm   = wid & 3;          // m-tile: 16 rows
    int wn   = wid >> 2;         // n-quarter: 32 cols
    int g    = lane >> 2;
    int tg2  = (lane & 3) * 2;

    unsigned sbaseA = (unsigned)__cvta_generic_to_shared(Asm);

    // ---- stage weights once (bf16) ----
    for (int idx = tid; idx < KK * D / 4; idx += 512) {
        int k  = idx >> 5;
        int c4 = (idx & 31) * 4;
        const float* src = (k < D) ? (Wa + (size_t)k * D) : (Wx + (size_t)(k - D) * D);
        float4 v = *reinterpret_cast<const float4*>(src + c4);
        *reinterpret_cast<__nv_bfloat162*>(&Bs[k * BS + c4])     = __floats2bfloat162_rn(v.x, v.y);
        *reinterpret_cast<__nv_bfloat162*>(&Bs[k * BS + c4 + 2]) = __floats2bfloat162_rn(v.z, v.w);
    }

    float resv = __ldg(resp);
    int stride = gridDim.x;

    // ---- prologue: stage first tile into buf 0 ----
    int t0 = blockIdx.x;
    {
        int row0 = t0 * BM;
        for (int i = tid; i < BM * 64; i += 512) {
            int r = i >> 6, c = i & 63;            // c = 16B chunk within row
            int row = row0 + r;
            const float* src = (c < 32) ? (agg + (size_t)row * D + c * 4)
                                        : (x   + (size_t)row * D + (c - 32) * 4);
            cp16(sbaseA + (unsigned)(r * ASF + c * 4) * 4, src, (row < Nn) ? 16 : 0);
        }
        asm volatile("cp.async.commit_group;" ::: "memory");
    }

    int buf = 0;
    for (int t = t0; t < ntiles; t += stride) {
        int row0 = t * BM;
        int tn = t + stride;
        // issue next tile into the other buffer (overlaps with this tile's MMA)
        if (tn < ntiles) {
            int nrow0 = tn * BM;
            unsigned sb = sbaseA + (unsigned)((buf ^ 1) * BM * ASF) * 4;
            for (int i = tid; i < BM * 64; i += 512) {
                int r = i >> 6, c = i & 63;
                int row = nrow0 + r;
                const float* src = (c < 32) ? (agg + (size_t)row * D + c * 4)
                                            : (x   + (size_t)row * D + (c - 32) * 4);
                cp16(sb + (unsigned)(r * ASF + c * 4) * 4, src, (row < Nn) ? 16 : 0);
            }
            asm volatile("cp.async.commit_group;" ::: "memory");
            asm volatile("cp.async.wait_group 1;" ::: "memory");
        } else {
            asm volatile("cp.async.wait_group 0;" ::: "memory");
        }
        __syncthreads();   // current buf ready for all warps (covers B on iter 0)

        const float* Ab = Asm + buf * BM * ASF;
        int r0l = wm * 16 + g;        // local rows this thread owns
        int r1l = r0l + 8;
        int r0g = row0 + r0l, r1g = row0 + r1l;
        float inv0 = g_inv[min(r0g, Nn - 1)];
        float inv1 = g_inv[min(r1g, Nn - 1)];

        float acc[4][4];
        #pragma unroll
        for (int j = 0; j < 4; j++)
            #pragma unroll
            for (int q = 0; q < 4; q++) acc[j][q] = 0.f;

        int brow = (lane & 7) + ((lane >> 3) & 1) * 8;
        int bcol = wn * 32 + ((lane >> 4) & 1) * 8;

        #pragma unroll
        for (int kk = 0; kk < KK; kk += 16) {
            float s0 = (kk < D) ? inv0 : 1.0f;
            float s1 = (kk < D) ? inv1 : 1.0f;
            // A fragment: direct LDS.64 + scale + cvt (m16n8k16 layout)
            float2 f0 = *reinterpret_cast<const float2*>(&Ab[r0l * ASF + kk + tg2]);
            float2 f1 = *reinterpret_cast<const float2*>(&Ab[r1l * ASF + kk + tg2]);
            float2 f2 = *reinterpret_cast<const float2*>(&Ab[r0l * ASF + kk + 8 + tg2]);
            float2 f3 = *reinterpret_cast<const float2*>(&Ab[r1l * ASF + kk + 8 + tg2]);
            __nv_bfloat162 h0 = __floats2bfloat162_rn(f0.x * s0, f0.y * s0);
            __nv_bfloat162 h1 = __floats2bfloat162_rn(f1.x * s1, f1.y * s1);
            __nv_bfloat162 h2 = __floats2bfloat162_rn(f2.x * s0, f2.y * s0);
            __nv_bfloat162 h3 = __floats2bfloat162_rn(f3.x * s1, f3.y * s1);
            unsigned a0 = *reinterpret_cast<unsigned*>(&h0);
            unsigned a1 = *reinterpret_cast<unsigned*>(&h1);
            unsigned a2 = *reinterpret_cast<unsigned*>(&h2);
            unsigned a3 = *reinterpret_cast<unsigned*>(&h3);

            #pragma unroll
            for (int nt = 0; nt < 2; nt++) {
                unsigned b0, b1, b2, b3;
                unsigned bd = (unsigned)__cvta_generic_to_shared(
                    &Bs[(size_t)(kk + brow) * BS + bcol + nt * 16]);
                asm volatile(
                    "ldmatrix.sync.aligned.m8n8.x4.trans.shared.b16 {%0,%1,%2,%3}, [%4];"
                    : "=r"(b0), "=r"(b1), "=r"(b2), "=r"(b3) : "r"(bd));
                asm volatile(
                    "mma.sync.aligned.m16n8k16.row.col.f32.bf16.bf16.f32 "
                    "{%0,%1,%2,%3}, {%4,%5,%6,%7}, {%8,%9}, {%0,%1,%2,%3};"
                    : "+f"(acc[nt*2][0]), "+f"(acc[nt*2][1]),
                      "+f"(acc[nt*2][2]), "+f"(acc[nt*2][3])
                    : "r"(a0), "r"(a1), "r"(a2), "r"(a3), "r"(b0), "r"(b1));
                asm volatile(
                    "mma.sync.aligned.m16n8k16.row.col.f32.bf16.bf16.f32 "
                    "{%0,%1,%2,%3}, {%4,%5,%6,%7}, {%8,%9}, {%0,%1,%2,%3};"
                    : "+f"(acc[nt*2+1][0]), "+f"(acc[nt*2+1][1]),
                      "+f"(acc[nt*2+1][2]), "+f"(acc[nt*2+1][3])
                    : "r"(a0), "r"(a1), "r"(a2), "r"(a3), "r"(b2), "r"(b3));
            }
        }

        // ---- epilogue: out = x(smem fp32) + res * tanh(acc) ----
        #pragma unroll
        for (int j = 0; j < 4; j++) {
            int col = wn * 32 + j * 8 + tg2;
            if (r0g < Nn) {
                float2 xv = *reinterpret_cast<const float2*>(&Ab[r0l * ASF + D + col]);
                float2 o;
                o.x = xv.x + resv * tanh_approx(acc[j][0]);
                o.y = xv.y + resv * tanh_approx(acc[j][1]);
                *reinterpret_cast<float2*>(out + (size_t)r0g * D + col) = o;
            }
            if (r1g < Nn) {
                float2 xv = *reinterpret_cast<const float2*>(&Ab[r1l * ASF + D + col]);
                float2 o;
                o.x = xv.x + resv * tanh_approx(acc[j][2]);
                o.y = xv.y + resv * tanh_approx(acc[j][3]);
                *reinterpret_cast<float2*>(out + (size_t)r1g * D + col) = o;
            }
        }
        __syncthreads();   // all reads of buf done before next issue overwrites peer buf
        buf ^= 1;
    }
}

// ---------------------------------------------------------------------------
extern "C" void kernel_launch(void* const* d_in, const int* in_sizes, int n_in,
                              void* d_out, int out_size)
{
    const float* emb    = (const float*)d_in[0];
    const float* change = (const float*)d_in[1];
    const float* W1     = (const float*)d_in[2];
    const float* Wl1    = (const float*)d_in[3];
    const float* rel1   = (const float*)d_in[4];
    const float* W2     = (const float*)d_in[5];
    const float* Wl2    = (const float*)d_in[6];
    const float* rel2   = (const float*)d_in[7];
    const float* res    = (const float*)d_in[8];
    const float* jw     = (const float*)d_in[9];
    const float* ewj    = (const float*)d_in[10];
    const int*   ei     = (const int*)d_in[11];
    const int*   et     = (const int*)d_in[12];
    const int*   ej     = (const int*)d_in[13];

    int Nn = in_sizes[0] / D;
    int E  = in_sizes[12];
    int EJ = in_sizes[10];
    int ntiles = (Nn + BM - 1) / BM;
    size_t rowBytes = (size_t)Nn * D * sizeof(float);

    float* out_change = (float*)d_out;
    float* out_dch    = (float*)d_out + (size_t)Nn * D;

    void *p_agg1, *p_agg2, *p_h, *p_deg;
    cudaGetSymbolAddress(&p_agg1, g_agg1);
    cudaGetSymbolAddress(&p_agg2, g_agg2);
    cudaGetSymbolAddress(&p_h,    g_h);
    cudaGetSymbolAddress(&p_deg,  g_deg);
    float* agg1 = (float*)p_agg1;
    float* agg2 = (float*)p_agg2;
    float* hbuf = (float*)p_h;

    cudaFuncSetAttribute(fused_gemm, cudaFuncAttributeMaxDynamicSharedMemorySize,
                         SMEM_BYTES);

    // Serial spine — every phase is bandwidth-bound; minimize total bytes.
    cudaMemsetAsync(p_deg,  0, (size_t)Nn * sizeof(float), 0);
    cudaMemsetAsync(p_agg1, 0, rowBytes, 0);
    deg_count<<<(E + 255) / 256, 256>>>(ei, E);
    inv_deg_k<<<(Nn + 255) / 256, 256>>>(Nn);

    // Layer 1
    conv_scatter<<<4736, 256>>>(emb, rel1, ei, et, agg1, E);
    fused_gemm<<<152, 512, SMEM_BYTES>>>(emb, W1, Wl1, res, agg1, hbuf, Nn, ntiles);

    // Layer 2
    cudaMemsetAsync(p_agg2, 0, rowBytes, 0);
    conv_scatter<<<4736, 256>>>(hbuf, rel2, ei, et, agg2, E);
    fused_gemm<<<152, 512, SMEM_BYTES>>>(hbuf, W2, Wl2, res, agg2, out_dch, Nn, ntiles);

    // Jump diffusion accumulates directly onto dchange
    jump_scatter<<<2368, 256>>>(emb, ewj, jw, ej, out_dch, EJ);

    // change passthrough
    cudaMemcpyAsync(out_change, change, rowBytes, cudaMemcpyDeviceToDevice, 0);
}

// round 6
// speedup vs baseline: 2.0461x; 1.0479x over previous
#include <cuda_runtime.h>
#include <cuda_bf16.h>
#include <math.h>

#define D 128
#define NMAX 100000
#define EMAX 620000
#define SCAN_B 512

// Static scratch (no allocations allowed)
__device__ float g_agg[(size_t)NMAX * D];     // shared by both layers
__device__ float g_h  [(size_t)NMAX * D];
__device__ int   g_cnt [NMAX];
__device__ int   g_fcnt[NMAX];
__device__ int   g_ptr [NMAX + 1];
__device__ int   g_bsum[256];
__device__ int   g_boff[256];
__device__ int2  g_ebuf[EMAX];

__device__ __forceinline__ void red_add_v4(float* p, float4 v) {
    asm volatile("red.global.add.v4.f32 [%0], {%1,%2,%3,%4};"
                 :: "l"(p), "f"(v.x), "f"(v.y), "f"(v.z), "f"(v.w) : "memory");
}

__device__ __forceinline__ float tanh_approx(float x) {
    float y;
    asm("tanh.approx.f32 %0, %1;" : "=f"(y) : "f"(x));
    return y;
}

__device__ __forceinline__ void cp16(unsigned saddr, const void* g, int srcsize) {
    asm volatile("cp.async.cg.shared.global [%0], [%1], 16, %2;"
                 :: "r"(saddr), "l"(g), "r"(srcsize));
}

// ---------------------------------------------------------------------------
// CSR build: degree histogram -> exclusive scan -> bucket fill
// ---------------------------------------------------------------------------
__global__ void deg_count(const int* __restrict__ ei, int E) {
    int i = blockIdx.x * blockDim.x + threadIdx.x;
    if (i < E) atomicAdd(&g_cnt[__ldg(ei + E + i)], 1);
}

__global__ void scan1(int Nn) {
    __shared__ int warpsums[16];
    int i = blockIdx.x * SCAN_B + threadIdx.x;
    int lane = threadIdx.x & 31, w = threadIdx.x >> 5;
    int v = (i < Nn) ? g_cnt[i] : 0;
    int s = v;
    #pragma unroll
    for (int o = 1; o < 32; o <<= 1) {
        int t = __shfl_up_sync(~0u, s, o);
        if (lane >= o) s += t;
    }
    if (lane == 31) warpsums[w] = s;
    __syncthreads();
    if (w == 0) {
        int ws = (lane < 16) ? warpsums[lane] : 0;
        #pragma unroll
        for (int o = 1; o < 16; o <<= 1) {
            int t = __shfl_up_sync(~0u, ws, o);
            if (lane >= o) ws += t;
        }
        if (lane < 16) warpsums[lane] = ws;
    }
    __syncthreads();
    int base = (w > 0) ? warpsums[w - 1] : 0;
    if (i < Nn) g_ptr[i] = base + s - v;              // block-local exclusive
    if (threadIdx.x == SCAN_B - 1) g_bsum[blockIdx.x] = base + s;
}

__global__ void scan2(int nb) {
    if (threadIdx.x == 0 && blockIdx.x == 0) {
        int acc = 0;
        for (int b = 0; b < nb; b++) { g_boff[b] = acc; acc += g_bsum[b]; }
    }
}

__global__ void scan3(int Nn, int E) {
    int i = blockIdx.x * blockDim.x + threadIdx.x;
    if (i < Nn) g_ptr[i] += g_boff[i / SCAN_B];
    if (i == 0) g_ptr[Nn] = E;
}

__global__ void csr_fill(const int* __restrict__ ei, const int* __restrict__ et, int E) {
    int e = blockIdx.x * blockDim.x + threadIdx.x;
    if (e < E) {
        int dst = __ldg(ei + E + e);
        int p = g_ptr[dst] + atomicAdd(&g_fcnt[dst], 1);
        g_ebuf[p] = make_int2(__ldg(ei + e), __ldg(et + e));
    }
}

// ---------------------------------------------------------------------------
// Gather conv: one warp per destination node; writes NORMALIZED agg.
// ---------------------------------------------------------------------------
__global__ __launch_bounds__(256)
void conv_gather(const float* __restrict__ x,
                 const float* __restrict__ rel,
                 float* __restrict__ agg,
                 int Nn)
{
    int node = blockIdx.x * (blockDim.x >> 5) + (threadIdx.x >> 5);
    if (node >= Nn) return;
    int lane = threadIdx.x & 31;
    int beg = __ldg(&g_ptr[node]);
    int end = __ldg(&g_ptr[node + 1]);
    float4 acc = make_float4(0.f, 0.f, 0.f, 0.f);
    for (int i = beg; i < end; i++) {
        int2 e = __ldg(&g_ebuf[i]);
        float4 xv = reinterpret_cast<const float4*>(x   + (size_t)e.x * D)[lane];
        float4 rv = reinterpret_cast<const float4*>(rel + (size_t)e.y * D)[lane];
        acc.x += xv.x * rv.x; acc.y += xv.y * rv.y;
        acc.z += xv.z * rv.z; acc.w += xv.w * rv.w;
    }
    float inv = 1.0f / fmaxf((float)(end - beg), 1.0f);
    acc.x *= inv; acc.y *= inv; acc.z *= inv; acc.w *= inv;
    reinterpret_cast<float4*>(agg + (size_t)node * D)[lane] = acc;
}

// ---------------------------------------------------------------------------
// Jump scatter: out[dst] += jw * ew[e] * emb[src]
// ---------------------------------------------------------------------------
__global__ __launch_bounds__(256)
void jump_scatter(const float* __restrict__ emb,
                  const float* __restrict__ ew,
                  const float* __restrict__ jwp,
                  const int* __restrict__ ej,
                  float* __restrict__ out, int EJ)
{
    float jw = __ldg(jwp);
    int lane = threadIdx.x & 31;
    int warp = blockIdx.x * (blockDim.x >> 5) + (threadIdx.x >> 5);
    int nwarps = gridDim.x * (blockDim.x >> 5);
    for (int e = warp; e < EJ; e += nwarps) {
        int src = __ldg(ej + e);
        int dst = __ldg(ej + EJ + e);
        float w = jw * __ldg(ew + e);
        float4 v = reinterpret_cast<const float4*>(emb + (size_t)src * D)[lane];
        v.x *= w; v.y *= w; v.z *= w; v.w *= w;
        red_add_v4(out + (size_t)dst * D + lane * 4, v);
    }
}

// ---------------------------------------------------------------------------
// Pipelined fused GEMM:  out = x + res * tanh( agg @ Wa + x @ Wx )
// (agg arrives pre-normalized). A = [agg | x] staged raw fp32 via cp.async,
// double-buffered; bf16 cvt in fragment build; epilogue reads x from smem.
// ---------------------------------------------------------------------------
#define BM 64
#define KK 256
#define ASF 260
#define BS  136
#define SMEM_A_BYTES (2 * BM * ASF * 4)
#define SMEM_B_BYTES (KK * BS * 2)
#define SMEM_BYTES   (SMEM_A_BYTES + SMEM_B_BYTES)

__global__ __launch_bounds__(512, 1)
void fused_gemm(const float* __restrict__ x,
                const float* __restrict__ Wa,
                const float* __restrict__ Wx,
                const float* __restrict__ resp,
                const float* __restrict__ agg,
                float* __restrict__ out,
                int Nn, int ntiles)
{
    extern __shared__ char smraw[];
    float* Asm = reinterpret_cast<float*>(smraw);
    __nv_bfloat16* Bs = reinterpret_cast<__nv_bfloat16*>(smraw + SMEM_A_BYTES);

    int tid  = threadIdx.x;
    int lane = tid & 31;
    int wid  = tid >> 5;
    int wm   = wid & 3;
    int wn   = wid >> 2;
    int g    = lane >> 2;
    int tg2  = (lane & 3) * 2;

    unsigned sbaseA = (unsigned)__cvta_generic_to_shared(Asm);

    for (int idx = tid; idx < KK * D / 4; idx += 512) {
        int k  = idx >> 5;
        int c4 = (idx & 31) * 4;
        const float* src = (k < D) ? (Wa + (size_t)k * D) : (Wx + (size_t)(k - D) * D);
        float4 v = *reinterpret_cast<const float4*>(src + c4);
        *reinterpret_cast<__nv_bfloat162*>(&Bs[k * BS + c4])     = __floats2bfloat162_rn(v.x, v.y);
        *reinterpret_cast<__nv_bfloat162*>(&Bs[k * BS + c4 + 2]) = __floats2bfloat162_rn(v.z, v.w);
    }

    float resv = __ldg(resp);
    int stride = gridDim.x;

    int t0 = blockIdx.x;
    {
        int row0 = t0 * BM;
        for (int i = tid; i < BM * 64; i += 512) {
            int r = i >> 6, c = i & 63;
            int row = row0 + r;
            const float* src = (c < 32) ? (agg + (size_t)row * D + c * 4)
                                        : (x   + (size_t)row * D + (c - 32) * 4);
            cp16(sbaseA + (unsigned)(r * ASF + c * 4) * 4, src, (row < Nn) ? 16 : 0);
        }
        asm volatile("cp.async.commit_group;" ::: "memory");
    }

    int buf = 0;
    for (int t = t0; t < ntiles; t += stride) {
        int row0 = t * BM;
        int tn = t + stride;
        if (tn < ntiles) {
            int nrow0 = tn * BM;
            unsigned sb = sbaseA + (unsigned)((buf ^ 1) * BM * ASF) * 4;
            for (int i = tid; i < BM * 64; i += 512) {
                int r = i >> 6, c = i & 63;
                int row = nrow0 + r;
                const float* src = (c < 32) ? (agg + (size_t)row * D + c * 4)
                                            : (x   + (size_t)row * D + (c - 32) * 4);
                cp16(sb + (unsigned)(r * ASF + c * 4) * 4, src, (row < Nn) ? 16 : 0);
            }
            asm volatile("cp.async.commit_group;" ::: "memory");
            asm volatile("cp.async.wait_group 1;" ::: "memory");
        } else {
            asm volatile("cp.async.wait_group 0;" ::: "memory");
        }
        __syncthreads();

        const float* Ab = Asm + buf * BM * ASF;
        int r0l = wm * 16 + g;
        int r1l = r0l + 8;
        int r0g = row0 + r0l, r1g = row0 + r1l;

        float acc[4][4];
        #pragma unroll
        for (int j = 0; j < 4; j++)
            #pragma unroll
            for (int q = 0; q < 4; q++) acc[j][q] = 0.f;

        int brow = (lane & 7) + ((lane >> 3) & 1) * 8;
        int bcol = wn * 32 + ((lane >> 4) & 1) * 8;

        #pragma unroll
        for (int kk = 0; kk < KK; kk += 16) {
            float2 f0 = *reinterpret_cast<const float2*>(&Ab[r0l * ASF + kk + tg2]);
            float2 f1 = *reinterpret_cast<const float2*>(&Ab[r1l * ASF + kk + tg2]);
            float2 f2 = *reinterpret_cast<const float2*>(&Ab[r0l * ASF + kk + 8 + tg2]);
            float2 f3 = *reinterpret_cast<const float2*>(&Ab[r1l * ASF + kk + 8 + tg2]);
            __nv_bfloat162 h0 = __floats2bfloat162_rn(f0.x, f0.y);
            __nv_bfloat162 h1 = __floats2bfloat162_rn(f1.x, f1.y);
            __nv_bfloat162 h2 = __floats2bfloat162_rn(f2.x, f2.y);
            __nv_bfloat162 h3 = __floats2bfloat162_rn(f3.x, f3.y);
            unsigned a0 = *reinterpret_cast<unsigned*>(&h0);
            unsigned a1 = *reinterpret_cast<unsigned*>(&h1);
            unsigned a2 = *reinterpret_cast<unsigned*>(&h2);
            unsigned a3 = *reinterpret_cast<unsigned*>(&h3);

            #pragma unroll
            for (int nt = 0; nt < 2; nt++) {
                unsigned b0, b1, b2, b3;
                unsigned bd = (unsigned)__cvta_generic_to_shared(
                    &Bs[(size_t)(kk + brow) * BS + bcol + nt * 16]);
                asm volatile(
                    "ldmatrix.sync.aligned.m8n8.x4.trans.shared.b16 {%0,%1,%2,%3}, [%4];"
                    : "=r"(b0), "=r"(b1), "=r"(b2), "=r"(b3) : "r"(bd));
                asm volatile(
                    "mma.sync.aligned.m16n8k16.row.col.f32.bf16.bf16.f32 "
                    "{%0,%1,%2,%3}, {%4,%5,%6,%7}, {%8,%9}, {%0,%1,%2,%3};"
                    : "+f"(acc[nt*2][0]), "+f"(acc[nt*2][1]),
                      "+f"(acc[nt*2][2]), "+f"(acc[nt*2][3])
                    : "r"(a0), "r"(a1), "r"(a2), "r"(a3), "r"(b0), "r"(b1));
                asm volatile(
                    "mma.sync.aligned.m16n8k16.row.col.f32.bf16.bf16.f32 "
                    "{%0,%1,%2,%3}, {%4,%5,%6,%7}, {%8,%9}, {%0,%1,%2,%3};"
                    : "+f"(acc[nt*2+1][0]), "+f"(acc[nt*2+1][1]),
                      "+f"(acc[nt*2+1][2]), "+f"(acc[nt*2+1][3])
                    : "r"(a0), "r"(a1), "r"(a2), "r"(a3), "r"(b2), "r"(b3));
            }
        }

        #pragma unroll
        for (int j = 0; j < 4; j++) {
            int col = wn * 32 + j * 8 + tg2;
            if (r0g < Nn) {
                float2 xv = *reinterpret_cast<const float2*>(&Ab[r0l * ASF + D + col]);
                float2 o;
                o.x = xv.x + resv * tanh_approx(acc[j][0]);
                o.y = xv.y + resv * tanh_approx(acc[j][1]);
                *reinterpret_cast<float2*>(out + (size_t)r0g * D + col) = o;
            }
            if (r1g < Nn) {
                float2 xv = *reinterpret_cast<const float2*>(&Ab[r1l * ASF + D + col]);
                float2 o;
                o.x = xv.x + resv * tanh_approx(acc[j][2]);
                o.y = xv.y + resv * tanh_approx(acc[j][3]);
                *reinterpret_cast<float2*>(out + (size_t)r1g * D + col) = o;
            }
        }
        __syncthreads();
        buf ^= 1;
    }
}

// ---------------------------------------------------------------------------
extern "C" void kernel_launch(void* const* d_in, const int* in_sizes, int n_in,
                              void* d_out, int out_size)
{
    const float* emb    = (const float*)d_in[0];
    const float* change = (const float*)d_in[1];
    const float* W1     = (const float*)d_in[2];
    const float* Wl1    = (const float*)d_in[3];
    const float* rel1   = (const float*)d_in[4];
    const float* W2     = (const float*)d_in[5];
    const float* Wl2    = (const float*)d_in[6];
    const float* rel2   = (const float*)d_in[7];
    const float* res    = (const float*)d_in[8];
    const float* jw     = (const float*)d_in[9];
    const float* ewj    = (const float*)d_in[10];
    const int*   ei     = (const int*)d_in[11];
    const int*   et     = (const int*)d_in[12];
    const int*   ej     = (const int*)d_in[13];

    int Nn = in_sizes[0] / D;
    int E  = in_sizes[12];
    int EJ = in_sizes[10];
    int ntiles = (Nn + BM - 1) / BM;
    int nscan = (Nn + SCAN_B - 1) / SCAN_B;
    size_t rowBytes = (size_t)Nn * D * sizeof(float);

    float* out_change = (float*)d_out;
    float* out_dch    = (float*)d_out + (size_t)Nn * D;

    void *p_agg, *p_h, *p_cnt, *p_fcnt;
    cudaGetSymbolAddress(&p_agg, g_agg);
    cudaGetSymbolAddress(&p_h,   g_h);
    cudaGetSymbolAddress(&p_cnt, g_cnt);
    cudaGetSymbolAddress(&p_fcnt, g_fcnt);
    float* agg  = (float*)p_agg;
    float* hbuf = (float*)p_h;

    cudaFuncSetAttribute(fused_gemm, cudaFuncAttributeMaxDynamicSharedMemorySize,
                         SMEM_BYTES);

    int convBlocks = (Nn + 7) / 8;   // 8 warps per 256-thread block

    // ---- CSR build (edge_index/edge_type shared by both layers) ----
    cudaMemsetAsync(p_cnt,  0, (size_t)Nn * sizeof(int), 0);
    cudaMemsetAsync(p_fcnt, 0, (size_t)Nn * sizeof(int), 0);
    deg_count<<<(E + 255) / 256, 256>>>(ei, E);
    scan1<<<nscan, SCAN_B>>>(Nn);
    scan2<<<1, 32>>>(nscan);
    scan3<<<(Nn + 255) / 256, 256>>>(Nn, E);
    csr_fill<<<(E + 255) / 256, 256>>>(ei, et, E);

    // Layer 1
    conv_gather<<<convBlocks, 256>>>(emb, rel1, agg, Nn);
    fused_gemm<<<152, 512, SMEM_BYTES>>>(emb, W1, Wl1, res, agg, hbuf, Nn, ntiles);

    // Layer 2 (reuse agg buffer: stays L2-resident)
    conv_gather<<<convBlocks, 256>>>(hbuf, rel2, agg, Nn);
    fused_gemm<<<152, 512, SMEM_BYTES>>>(hbuf, W2, Wl2, res, agg, out_dch, Nn, ntiles);

    // Jump diffusion accumulates directly onto dchange
    jump_scatter<<<2368, 256>>>(emb, ewj, jw, ej, out_dch, EJ);

    // change passthrough
    cudaMemcpyAsync(out_change, change, rowBytes, cudaMemcpyDeviceToDevice, 0);
}

// round 8
// speedup vs baseline: 2.2403x; 1.0949x over previous
#include <cuda_runtime.h>
#include <cuda_bf16.h>
#include <math.h>

#define D 128
#define NMAX 100000
#define EMAX 620000
#define SCAN_B 512

// Static scratch (no allocations allowed)
__device__ __nv_bfloat16 g_aggbf[(size_t)NMAX * D];   // 25.6 MB, both layers
__device__ float g_h[(size_t)NMAX * D];
__device__ int   g_cnt [NMAX];
__device__ int   g_fcnt[NMAX];
__device__ int   g_ptr [NMAX + 1];
__device__ int   g_bsum[256];
__device__ int   g_boff[256];
__device__ unsigned g_ebuf[EMAX];                      // src | (type<<17)

__device__ __forceinline__ void red_add_v4(float* p, float4 v) {
    asm volatile("red.global.add.v4.f32 [%0], {%1,%2,%3,%4};"
                 :: "l"(p), "f"(v.x), "f"(v.y), "f"(v.z), "f"(v.w) : "memory");
}

__device__ __forceinline__ float tanh_approx(float x) {
    float y;
    asm("tanh.approx.f32 %0, %1;" : "=f"(y) : "f"(x));
    return y;
}

__device__ __forceinline__ void cp16(unsigned saddr, const void* g, int srcsize) {
    asm volatile("cp.async.cg.shared.global [%0], [%1], 16, %2;"
                 :: "r"(saddr), "l"(g), "r"(srcsize));
}

// ---------------------------------------------------------------------------
// CSR build
// ---------------------------------------------------------------------------
__global__ void deg_count(const int* __restrict__ ei, int E) {
    int i = blockIdx.x * blockDim.x + threadIdx.x;
    if (i < E) atomicAdd(&g_cnt[__ldg(ei + E + i)], 1);
}

__global__ void scan1(int Nn) {
    __shared__ int warpsums[16];
    int i = blockIdx.x * SCAN_B + threadIdx.x;
    int lane = threadIdx.x & 31, w = threadIdx.x >> 5;
    int v = (i < Nn) ? g_cnt[i] : 0;
    int s = v;
    #pragma unroll
    for (int o = 1; o < 32; o <<= 1) {
        int t = __shfl_up_sync(~0u, s, o);
        if (lane >= o) s += t;
    }
    if (lane == 31) warpsums[w] = s;
    __syncthreads();
    if (w == 0) {
        int ws = (lane < 16) ? warpsums[lane] : 0;
        #pragma unroll
        for (int o = 1; o < 16; o <<= 1) {
            int t = __shfl_up_sync(~0u, ws, o);
            if (lane >= o) ws += t;
        }
        if (lane < 16) warpsums[lane] = ws;
    }
    __syncthreads();
    int base = (w > 0) ? warpsums[w - 1] : 0;
    if (i < Nn) g_ptr[i] = base + s - v;
    if (threadIdx.x == SCAN_B - 1) g_bsum[blockIdx.x] = base + s;
}

__global__ void scan2(int nb) {
    if (threadIdx.x == 0 && blockIdx.x == 0) {
        int acc = 0;
        for (int b = 0; b < nb; b++) { g_boff[b] = acc; acc += g_bsum[b]; }
    }
}

__global__ void scan3(int Nn, int E) {
    int i = blockIdx.x * blockDim.x + threadIdx.x;
    if (i < Nn) g_ptr[i] += g_boff[i / SCAN_B];
    if (i == 0) g_ptr[Nn] = E;
}

__global__ void csr_fill(const int* __restrict__ ei, const int* __restrict__ et, int E) {
    int e = blockIdx.x * blockDim.x + threadIdx.x;
    if (e < E) {
        int dst = __ldg(ei + E + e);
        int p = g_ptr[dst] + atomicAdd(&g_fcnt[dst], 1);
        g_ebuf[p] = (unsigned)__ldg(ei + e) | ((unsigned)__ldg(et + e) << 17);
    }
}

// ---------------------------------------------------------------------------
// Gather conv: warp per destination; writes NORMALIZED agg in bf16.
// (bf16 rounding here == the rounding gemm did anyway: numerically identical.)
// ---------------------------------------------------------------------------
__global__ __launch_bounds__(256)
void conv_gather(const float* __restrict__ x,
                 const float* __restrict__ rel,
                 __nv_bfloat16* __restrict__ agg,
                 int Nn)
{
    int node = blockIdx.x * (blockDim.x >> 5) + (threadIdx.x >> 5);
    if (node >= Nn) return;
    int lane = threadIdx.x & 31;
    int beg = __ldg(&g_ptr[node]);
    int end = __ldg(&g_ptr[node + 1]);
    float4 acc = make_float4(0.f, 0.f, 0.f, 0.f);
    for (int i = beg; i < end; i++) {
        unsigned e = __ldg(&g_ebuf[i]);
        int src = e & 0x1FFFF;
        int typ = e >> 17;
        float4 xv = reinterpret_cast<const float4*>(x   + (size_t)src * D)[lane];
        float4 rv = reinterpret_cast<const float4*>(rel + (size_t)typ * D)[lane];
        acc.x += xv.x * rv.x; acc.y += xv.y * rv.y;
        acc.z += xv.z * rv.z; acc.w += xv.w * rv.w;
    }
    float inv = 1.0f / fmaxf((float)(end - beg), 1.0f);
    __nv_bfloat162 p01 = __floats2bfloat162_rn(acc.x * inv, acc.y * inv);
    __nv_bfloat162 p23 = __floats2bfloat162_rn(acc.z * inv, acc.w * inv);
    unsigned u0 = *reinterpret_cast<unsigned*>(&p01);
    unsigned u1 = *reinterpret_cast<unsigned*>(&p23);
    reinterpret_cast<uint2*>(agg + (size_t)node * D)[lane] = make_uint2(u0, u1);
}

// ---------------------------------------------------------------------------
// Jump scatter: out[dst] += jw * ew[e] * emb[src]
// ---------------------------------------------------------------------------
__global__ __launch_bounds__(256)
void jump_scatter(const float* __restrict__ emb,
                  const float* __restrict__ ew,
                  const float* __restrict__ jwp,
                  const int* __restrict__ ej,
                  float* __restrict__ out, int EJ)
{
    float jw = __ldg(jwp);
    int lane = threadIdx.x & 31;
    int warp = blockIdx.x * (blockDim.x >> 5) + (threadIdx.x >> 5);
    int nwarps = gridDim.x * (blockDim.x >> 5);
    for (int e = warp; e < EJ; e += nwarps) {
        int src = __ldg(ej + e);
        int dst = __ldg(ej + EJ + e);
        float w = jw * __ldg(ew + e);
        float4 v = reinterpret_cast<const float4*>(emb + (size_t)src * D)[lane];
        v.x *= w; v.y *= w; v.z *= w; v.w *= w;
        red_add_v4(out + (size_t)dst * D + lane * 4, v);
    }
}

// ---------------------------------------------------------------------------
// Pipelined fused GEMM:  out = x + res * tanh( aggbf @ Wa + x @ Wx )
// A split: agg half staged bf16 via cp.async (ldmatrix fragments),
//          x half staged fp32 (LDS+cvt fragments; epilogue reads it fp32).
// Double-buffered; 512 threads = 16 warps (4 m x 4 n).
// ---------------------------------------------------------------------------
#define BM 64
#define ASB 136                               // bf16 per agg row (272B, padded)
#define ASX 132                               // fp32 per x row (528B, padded)
#define BS  136
#define ABF_BYTES (BM * ASB * 2)              // 17408 per buf
#define AXF_BYTES (BM * ASX * 4)              // 33792 per buf
#define SMEM_B_OFF (2 * (ABF_BYTES + AXF_BYTES))   // 102400
#define SMEM_BYTES (SMEM_B_OFF + 256 * BS * 2)     // 172032

__global__ __launch_bounds__(512, 1)
void fused_gemm(const float* __restrict__ x,
                const float* __restrict__ Wa,
                const float* __restrict__ Wx,
                const float* __restrict__ resp,
                const __nv_bfloat16* __restrict__ aggbf,
                float* __restrict__ out,
                int Nn, int ntiles)
{
    extern __shared__ char smraw[];
    __nv_bfloat16* Abf = reinterpret_cast<__nv_bfloat16*>(smraw);          // [2][BM*ASB]
    float* Axf = reinterpret_cast<float*>(smraw + 2 * ABF_BYTES);          // [2][BM*ASX]
    __nv_bfloat16* Bs = reinterpret_cast<__nv_bfloat16*>(smraw + SMEM_B_OFF);

    int tid  = threadIdx.x;
    int lane = tid & 31;
    int wid  = tid >> 5;
    int wm   = wid & 3;
    int wn   = wid >> 2;
    int g    = lane >> 2;
    int tg2  = (lane & 3) * 2;

    unsigned sAbf = (unsigned)__cvta_generic_to_shared(Abf);
    unsigned sAxf = (unsigned)__cvta_generic_to_shared(Axf);

    // ---- stage weights once (bf16) ----
    for (int idx = tid; idx < 256 * D / 4; idx += 512) {
        int k  = idx >> 5;
        int c4 = (idx & 31) * 4;
        const float* src = (k < D) ? (Wa + (size_t)k * D) : (Wx + (size_t)(k - D) * D);
        float4 v = *reinterpret_cast<const float4*>(src + c4);
        *reinterpret_cast<__nv_bfloat162*>(&Bs[k * BS + c4])     = __floats2bfloat162_rn(v.x, v.y);
        *reinterpret_cast<__nv_bfloat162*>(&Bs[k * BS + c4 + 2]) = __floats2bfloat162_rn(v.z, v.w);
    }

    float resv = __ldg(resp);
    int stride = gridDim.x;

    // staging: 48 16B-chunks per row (16 agg-bf16 + 32 x-fp32), 64 rows
    auto stage = [&](int tile, int buf) {
        int row0 = tile * BM;
        unsigned b_bf = sAbf + (unsigned)buf * ABF_BYTES;
        unsigned b_xf = sAxf + (unsigned)buf * AXF_BYTES;
        for (int i = tid; i < BM * 48; i += 512) {
            int r = i / 48, c = i % 48;
            int row = row0 + r;
            int ok = (row < Nn) ? 16 : 0;
            if (c < 16) {
                cp16(b_bf + (unsigned)(r * ASB + c * 8) * 2,
                     aggbf + (size_t)row * D + c * 8, ok);
            } else {
                int cx = c - 16;
                cp16(b_xf + (unsigned)(r * ASX + cx * 4) * 4,
                     x + (size_t)row * D + cx * 4, ok);
            }
        }
        asm volatile("cp.async.commit_group;" ::: "memory");
    };

    int t0 = blockIdx.x;
    stage(t0, 0);

    int buf = 0;
    for (int t = t0; t < ntiles; t += stride) {
        int row0 = t * BM;
        int tn = t + stride;
        if (tn < ntiles) {
            stage(tn, buf ^ 1);
            asm volatile("cp.async.wait_group 1;" ::: "memory");
        } else {
            asm volatile("cp.async.wait_group 0;" ::: "memory");
        }
        __syncthreads();

        const __nv_bfloat16* Ab = Abf + buf * BM * ASB;
        const float* Ax = Axf + buf * BM * ASX;
        int r0l = wm * 16 + g;
        int r1l = r0l + 8;
        int r0g = row0 + r0l, r1g = row0 + r1l;

        float acc[4][4];
        #pragma unroll
        for (int j = 0; j < 4; j++)
            #pragma unroll
            for (int q = 0; q < 4; q++) acc[j][q] = 0.f;

        int arow = wm * 16 + (lane & 15);
        int acol = (lane >> 4) * 8;
        int brow = (lane & 7) + ((lane >> 3) & 1) * 8;
        int bcol = wn * 32 + ((lane >> 4) & 1) * 8;

        // ---- agg half: ldmatrix A fragments (k in [0,128)) ----
        #pragma unroll
        for (int kk = 0; kk < D; kk += 16) {
            unsigned a0, a1, a2, a3;
            unsigned ad = (unsigned)__cvta_generic_to_shared(
                &Ab[(size_t)arow * ASB + kk + acol]);
            asm volatile(
                "ldmatrix.sync.aligned.m8n8.x4.shared.b16 {%0,%1,%2,%3}, [%4];"
                : "=r"(a0), "=r"(a1), "=r"(a2), "=r"(a3) : "r"(ad));
            #pragma unroll
            for (int nt = 0; nt < 2; nt++) {
                unsigned b0, b1, b2, b3;
                unsigned bd = (unsigned)__cvta_generic_to_shared(
                    &Bs[(size_t)(kk + brow) * BS + bcol + nt * 16]);
                asm volatile(
                    "ldmatrix.sync.aligned.m8n8.x4.trans.shared.b16 {%0,%1,%2,%3}, [%4];"
                    : "=r"(b0), "=r"(b1), "=r"(b2), "=r"(b3) : "r"(bd));
                asm volatile(
                    "mma.sync.aligned.m16n8k16.row.col.f32.bf16.bf16.f32 "
                    "{%0,%1,%2,%3}, {%4,%5,%6,%7}, {%8,%9}, {%0,%1,%2,%3};"
                    : "+f"(acc[nt*2][0]), "+f"(acc[nt*2][1]),
                      "+f"(acc[nt*2][2]), "+f"(acc[nt*2][3])
                    : "r"(a0), "r"(a1), "r"(a2), "r"(a3), "r"(b0), "r"(b1));
                asm volatile(
                    "mma.sync.aligned.m16n8k16.row.col.f32.bf16.bf16.f32 "
                    "{%0,%1,%2,%3}, {%4,%5,%6,%7}, {%8,%9}, {%0,%1,%2,%3};"
                    : "+f"(acc[nt*2+1][0]), "+f"(acc[nt*2+1][1]),
                      "+f"(acc[nt*2+1][2]), "+f"(acc[nt*2+1][3])
                    : "r"(a0), "r"(a1), "r"(a2), "r"(a3), "r"(b2), "r"(b3));
            }
        }

        // ---- x half: LDS.64+cvt fragments (k in [128,256)) ----
        #pragma unroll
        for (int kk = D; kk < 256; kk += 16) {
            int kx = kk - D;
            float2 f0 = *reinterpret_cast<const float2*>(&Ax[r0l * ASX + kx + tg2]);
            float2 f1 = *reinterpret_cast<const float2*>(&Ax[r1l * ASX + kx + tg2]);
            float2 f2 = *reinterpret_cast<const float2*>(&Ax[r0l * ASX + kx + 8 + tg2]);
            float2 f3 = *reinterpret_cast<const float2*>(&Ax[r1l * ASX + kx + 8 + tg2]);
            __nv_bfloat162 h0 = __floats2bfloat162_rn(f0.x, f0.y);
            __nv_bfloat162 h1 = __floats2bfloat162_rn(f1.x, f1.y);
            __nv_bfloat162 h2 = __floats2bfloat162_rn(f2.x, f2.y);
            __nv_bfloat162 h3 = __floats2bfloat162_rn(f3.x, f3.y);
            unsigned a0 = *reinterpret_cast<unsigned*>(&h0);
            unsigned a1 = *reinterpret_cast<unsigned*>(&h1);
            unsigned a2 = *reinterpret_cast<unsigned*>(&h2);
            unsigned a3 = *reinterpret_cast<unsigned*>(&h3);
            #pragma unroll
            for (int nt = 0; nt < 2; nt++) {
                unsigned b0, b1, b2, b3;
                unsigned bd = (unsigned)__cvta_generic_to_shared(
                    &Bs[(size_t)(kk + brow) * BS + bcol + nt * 16]);
                asm volatile(
                    "ldmatrix.sync.aligned.m8n8.x4.trans.shared.b16 {%0,%1,%2,%3}, [%4];"
                    : "=r"(b0), "=r"(b1), "=r"(b2), "=r"(b3) : "r"(bd));
                asm volatile(
                    "mma.sync.aligned.m16n8k16.row.col.f32.bf16.bf16.f32 "
                    "{%0,%1,%2,%3}, {%4,%5,%6,%7}, {%8,%9}, {%0,%1,%2,%3};"
                    : "+f"(acc[nt*2][0]), "+f"(acc[nt*2][1]),
                      "+f"(acc[nt*2][2]), "+f"(acc[nt*2][3])
                    : "r"(a0), "r"(a1), "r"(a2), "r"(a3), "r"(b0), "r"(b1));
                asm volatile(
                    "mma.sync.aligned.m16n8k16.row.col.f32.bf16.bf16.f32 "
                    "{%0,%1,%2,%3}, {%4,%5,%6,%7}, {%8,%9}, {%0,%1,%2,%3};"
                    : "+f"(acc[nt*2+1][0]), "+f"(acc[nt*2+1][1]),
                      "+f"(acc[nt*2+1][2]), "+f"(acc[nt*2+1][3])
                    : "r"(a0), "r"(a1), "r"(a2), "r"(a3), "r"(b2), "r"(b3));
            }
        }

        // ---- epilogue: out = x(smem fp32) + res * tanh(acc) ----
        #pragma unroll
        for (int j = 0; j < 4; j++) {
            int col = wn * 32 + j * 8 + tg2;
            if (r0g < Nn) {
                float2 xv = *reinterpret_cast<const float2*>(&Ax[r0l * ASX + col]);
                float2 o;
                o.x = xv.x + resv * tanh_approx(acc[j][0]);
                o.y = xv.y + resv * tanh_approx(acc[j][1]);
                *reinterpret_cast<float2*>(out + (size_t)r0g * D + col) = o;
            }
            if (r1g < Nn) {
                float2 xv = *reinterpret_cast<const float2*>(&Ax[r1l * ASX + col]);
                float2 o;
                o.x = xv.x + resv * tanh_approx(acc[j][2]);
                o.y = xv.y + resv * tanh_approx(acc[j][3]);
                *reinterpret_cast<float2*>(out + (size_t)r1g * D + col) = o;
            }
        }
        __syncthreads();
        buf ^= 1;
    }
}

// ---------------------------------------------------------------------------
extern "C" void kernel_launch(void* const* d_in, const int* in_sizes, int n_in,
                              void* d_out, int out_size)
{
    const float* emb    = (const float*)d_in[0];
    const float* change = (const float*)d_in[1];
    const float* W1     = (const float*)d_in[2];
    const float* Wl1    = (const float*)d_in[3];
    const float* rel1   = (const float*)d_in[4];
    const float* W2     = (const float*)d_in[5];
    const float* Wl2    = (const float*)d_in[6];
    const float* rel2   = (const float*)d_in[7];
    const float* res    = (const float*)d_in[8];
    const float* jw     = (const float*)d_in[9];
    const float* ewj    = (const float*)d_in[10];
    const int*   ei     = (const int*)d_in[11];
    const int*   et     = (const int*)d_in[12];
    const int*   ej     = (const int*)d_in[13];

    int Nn = in_sizes[0] / D;
    int E  = in_sizes[12];
    int EJ = in_sizes[10];
    int ntiles = (Nn + BM - 1) / BM;
    int nscan = (Nn + SCAN_B - 1) / SCAN_B;
    size_t rowBytes = (size_t)Nn * D * sizeof(float);

    float* out_change = (float*)d_out;
    float* out_dch    = (float*)d_out + (size_t)Nn * D;

    void *p_agg, *p_h, *p_cnt, *p_fcnt;
    cudaGetSymbolAddress(&p_agg,  g_aggbf);
    cudaGetSymbolAddress(&p_h,    g_h);
    cudaGetSymbolAddress(&p_cnt,  g_cnt);
    cudaGetSymbolAddress(&p_fcnt, g_fcnt);
    __nv_bfloat16* agg = (__nv_bfloat16*)p_agg;
    float* hbuf = (float*)p_h;

    cudaFuncSetAttribute(fused_gemm, cudaFuncAttributeMaxDynamicSharedMemorySize,
                         SMEM_BYTES);

    int convBlocks = (Nn + 7) / 8;

    // ---- CSR build (shared by both layers) ----
    cudaMemsetAsync(p_cnt,  0, (size_t)Nn * sizeof(int), 0);
    cudaMemsetAsync(p_fcnt, 0, (size_t)Nn * sizeof(int), 0);
    deg_count<<<(E + 255) / 256, 256>>>(ei, E);
    scan1<<<nscan, SCAN_B>>>(Nn);
    scan2<<<1, 32>>>(nscan);
    scan3<<<(Nn + 255) / 256, 256>>>(Nn, E);
    csr_fill<<<(E + 255) / 256, 256>>>(ei, et, E);

    // Layer 1
    conv_gather<<<convBlocks, 256>>>(emb, rel1, agg, Nn);
    fused_gemm<<<152, 512, SMEM_BYTES>>>(emb, W1, Wl1, res, agg, hbuf, Nn, ntiles);

    // Layer 2 (agg buffer reused; stays L2-resident)
    conv_gather<<<convBlocks, 256>>>(hbuf, rel2, agg, Nn);
    fused_gemm<<<152, 512, SMEM_BYTES>>>(hbuf, W2, Wl2, res, agg, out_dch, Nn, ntiles);

    // Jump diffusion accumulates directly onto dchange
    jump_scatter<<<2368, 256>>>(emb, ewj, jw, ej, out_dch, EJ);

    // change passthrough
    cudaMemcpyAsync(out_change, change, rowBytes, cudaMemcpyDeviceToDevice, 0);
}

// round 11
// speedup vs baseline: 2.2534x; 1.0058x over previous
#include <cuda_runtime.h>
#include <cuda_bf16.h>
#include <math.h>

#define D 128
#define NMAX 100000
#define EMAX 620000
#define SCAN_B 512

// Static scratch (no allocations allowed)
__device__ __nv_bfloat16 g_aggbf[(size_t)NMAX * D];   // 25.6 MB, both layers
__device__ float g_h[(size_t)NMAX * D];
__device__ int   g_cnt [NMAX];
__device__ int   g_ptr [NMAX];     // exclusive prefix; post-fill: ptr[i]=excl[i+1]
__device__ int   g_bsum[256];
__device__ int   g_boff[256];
__device__ unsigned g_ebuf[EMAX];  // src | (type<<17)

__device__ __forceinline__ void red_add_v4(float* p, float4 v) {
    asm volatile("red.global.add.v4.f32 [%0], {%1,%2,%3,%4};"
                 :: "l"(p), "f"(v.x), "f"(v.y), "f"(v.z), "f"(v.w) : "memory");
}

__device__ __forceinline__ float tanh_approx(float x) {
    float y;
    asm("tanh.approx.f32 %0, %1;" : "=f"(y) : "f"(x));
    return y;
}

__device__ __forceinline__ void cp16(unsigned saddr, const void* g, int srcsize) {
    asm volatile("cp.async.cg.shared.global [%0], [%1], 16, %2;"
                 :: "r"(saddr), "l"(g), "r"(srcsize));
}

// ---------------------------------------------------------------------------
// CSR build
// ---------------------------------------------------------------------------
__global__ void deg_count(const int* __restrict__ ei, int E) {
    int i = blockIdx.x * blockDim.x + threadIdx.x;
    if (i < E) atomicAdd(&g_cnt[__ldg(ei + E + i)], 1);
}

__global__ void scan1(int Nn) {
    __shared__ int warpsums[16];
    int i = blockIdx.x * SCAN_B + threadIdx.x;
    int lane = threadIdx.x & 31, w = threadIdx.x >> 5;
    int v = (i < Nn) ? g_cnt[i] : 0;
    int s = v;
    #pragma unroll
    for (int o = 1; o < 32; o <<= 1) {
        int t = __shfl_up_sync(~0u, s, o);
        if (lane >= o) s += t;
    }
    if (lane == 31) warpsums[w] = s;
    __syncthreads();
    if (w == 0) {
        int ws = (lane < 16) ? warpsums[lane] : 0;
        #pragma unroll
        for (int o = 1; o < 16; o <<= 1) {
            int t = __shfl_up_sync(~0u, ws, o);
            if (lane >= o) ws += t;
        }
        if (lane < 16) warpsums[lane] = ws;
    }
    __syncthreads();
    int base = (w > 0) ? warpsums[w - 1] : 0;
    if (i < Nn) g_ptr[i] = base + s - v;
    if (threadIdx.x == SCAN_B - 1) g_bsum[blockIdx.x] = base + s;
}

__global__ void scan2(int nb) {
    if (threadIdx.x == 0 && blockIdx.x == 0) {
        int acc = 0;
        for (int b = 0; b < nb; b++) { g_boff[b] = acc; acc += g_bsum[b]; }
    }
}

__global__ void scan3(int Nn) {
    int i = blockIdx.x * blockDim.x + threadIdx.x;
    if (i < Nn) g_ptr[i] += g_boff[i / SCAN_B];
}

// Bumps g_ptr[dst] itself: afterwards ptr[i] == exclusive_prefix[i+1].
__global__ void csr_fill(const int* __restrict__ ei, const int* __restrict__ et, int E) {
    int e = blockIdx.x * blockDim.x + threadIdx.x;
    if (e < E) {
        int dst = __ldg(ei + E + e);
        int p = atomicAdd(&g_ptr[dst], 1);
        g_ebuf[p] = (unsigned)__ldg(ei + e) | ((unsigned)__ldg(et + e) << 17);
    }
}

// ---------------------------------------------------------------------------
// Gather conv: warp per destination; writes NORMALIZED agg in bf16.
// After csr_fill: beg = ptr[node-1] (0 for node 0), end = ptr[node].
// ---------------------------------------------------------------------------
__global__ __launch_bounds__(256)
void conv_gather(const float* __restrict__ x,
                 const float* __restrict__ rel,
                 __nv_bfloat16* __restrict__ agg,
                 int Nn)
{
    int node = blockIdx.x * (blockDim.x >> 5) + (threadIdx.x >> 5);
    if (node >= Nn) return;
    int lane = threadIdx.x & 31;
    int beg = (node == 0) ? 0 : __ldg(&g_ptr[node - 1]);
    int end = __ldg(&g_ptr[node]);
    float4 acc = make_float4(0.f, 0.f, 0.f, 0.f);
    for (int i = beg; i < end; i++) {
        unsigned e = __ldg(&g_ebuf[i]);
        int src = e & 0x1FFFF;
        int typ = e >> 17;
        float4 xv = reinterpret_cast<const float4*>(x   + (size_t)src * D)[lane];
        float4 rv = reinterpret_cast<const float4*>(rel + (size_t)typ * D)[lane];
        acc.x += xv.x * rv.x; acc.y += xv.y * rv.y;
        acc.z += xv.z * rv.z; acc.w += xv.w * rv.w;
    }
    float inv = 1.0f / fmaxf((float)(end - beg), 1.0f);
    __nv_bfloat162 p01 = __floats2bfloat162_rn(acc.x * inv, acc.y * inv);
    __nv_bfloat162 p23 = __floats2bfloat162_rn(acc.z * inv, acc.w * inv);
    unsigned u0 = *reinterpret_cast<unsigned*>(&p01);
    unsigned u1 = *reinterpret_cast<unsigned*>(&p23);
    reinterpret_cast<uint2*>(agg + (size_t)node * D)[lane] = make_uint2(u0, u1);
}

// ---------------------------------------------------------------------------
// Jump scatter: out[dst] += jw * ew[e] * emb[src]
// ---------------------------------------------------------------------------
__global__ __launch_bounds__(256)
void jump_scatter(const float* __restrict__ emb,
                  const float* __restrict__ ew,
                  const float* __restrict__ jwp,
                  const int* __restrict__ ej,
                  float* __restrict__ out, int EJ)
{
    float jw = __ldg(jwp);
    int lane = threadIdx.x & 31;
    int warp = blockIdx.x * (blockDim.x >> 5) + (threadIdx.x >> 5);
    int nwarps = gridDim.x * (blockDim.x >> 5);
    for (int e = warp; e < EJ; e += nwarps) {
        int src = __ldg(ej + e);
        int dst = __ldg(ej + EJ + e);
        float w = jw * __ldg(ew + e);
        float4 v = reinterpret_cast<const float4*>(emb + (size_t)src * D)[lane];
        v.x *= w; v.y *= w; v.z *= w; v.w *= w;
        red_add_v4(out + (size_t)dst * D + lane * 4, v);
    }
}

// ---------------------------------------------------------------------------
// Pipelined fused GEMM:  out = x + res * tanh( aggbf @ Wa + x @ Wx )
// A split: agg half staged bf16 via cp.async (ldmatrix fragments),
//          x half staged fp32 (LDS+cvt fragments; epilogue reads it fp32).
// Double-buffered; 512 threads = 16 warps (4 m x 4 n).
// ---------------------------------------------------------------------------
#define BM 64
#define ASB 136                               // bf16 per agg row (272B, padded)
#define ASX 132                               // fp32 per x row (528B, padded)
#define BS  136
#define ABF_BYTES (BM * ASB * 2)              // 17408 per buf
#define AXF_BYTES (BM * ASX * 4)              // 33792 per buf
#define SMEM_B_OFF (2 * (ABF_BYTES + AXF_BYTES))   // 102400
#define SMEM_BYTES (SMEM_B_OFF + 256 * BS * 2)     // 172032

__global__ __launch_bounds__(512, 1)
void fused_gemm(const float* __restrict__ x,
                const float* __restrict__ Wa,
                const float* __restrict__ Wx,
                const float* __restrict__ resp,
                const __nv_bfloat16* __restrict__ aggbf,
                float* __restrict__ out,
                int Nn, int ntiles)
{
    extern __shared__ char smraw[];
    __nv_bfloat16* Abf = reinterpret_cast<__nv_bfloat16*>(smraw);          // [2][BM*ASB]
    float* Axf = reinterpret_cast<float*>(smraw + 2 * ABF_BYTES);          // [2][BM*ASX]
    __nv_bfloat16* Bs = reinterpret_cast<__nv_bfloat16*>(smraw + SMEM_B_OFF);

    int tid  = threadIdx.x;
    int lane = tid & 31;
    int wid  = tid >> 5;
    int wm   = wid & 3;
    int wn   = wid >> 2;
    int g    = lane >> 2;
    int tg2  = (lane & 3) * 2;

    unsigned sAbf = (unsigned)__cvta_generic_to_shared(Abf);
    unsigned sAxf = (unsigned)__cvta_generic_to_shared(Axf);

    // ---- stage weights once (bf16) ----
    for (int idx = tid; idx < 256 * D / 4; idx += 512) {
        int k  = idx >> 5;
        int c4 = (idx & 31) * 4;
        const float* src = (k < D) ? (Wa + (size_t)k * D) : (Wx + (size_t)(k - D) * D);
        float4 v = *reinterpret_cast<const float4*>(src + c4);
        *reinterpret_cast<__nv_bfloat162*>(&Bs[k * BS + c4])     = __floats2bfloat162_rn(v.x, v.y);
        *reinterpret_cast<__nv_bfloat162*>(&Bs[k * BS + c4 + 2]) = __floats2bfloat162_rn(v.z, v.w);
    }

    float resv = __ldg(resp);
    int stride = gridDim.x;

    // staging: 48 16B-chunks per row (16 agg-bf16 + 32 x-fp32), 64 rows
    auto stage = [&](int tile, int buf) {
        int row0 = tile * BM;
        unsigned b_bf = sAbf + (unsigned)buf * ABF_BYTES;
        unsigned b_xf = sAxf + (unsigned)buf * AXF_BYTES;
        for (int i = tid; i < BM * 48; i += 512) {
            int r = i / 48, c = i % 48;
            int row = row0 + r;
            int ok = (row < Nn) ? 16 : 0;
            if (c < 16) {
                cp16(b_bf + (unsigned)(r * ASB + c * 8) * 2,
                     aggbf + (size_t)row * D + c * 8, ok);
            } else {
                int cx = c - 16;
                cp16(b_xf + (unsigned)(r * ASX + cx * 4) * 4,
                     x + (size_t)row * D + cx * 4, ok);
            }
        }
        asm volatile("cp.async.commit_group;" ::: "memory");
    };

    int t0 = blockIdx.x;
    stage(t0, 0);

    int buf = 0;
    for (int t = t0; t < ntiles; t += stride) {
        int row0 = t * BM;
        int tn = t + stride;
        if (tn < ntiles) {
            stage(tn, buf ^ 1);
            asm volatile("cp.async.wait_group 1;" ::: "memory");
        } else {
            asm volatile("cp.async.wait_group 0;" ::: "memory");
        }
        __syncthreads();

        const __nv_bfloat16* Ab = Abf + buf * BM * ASB;
        const float* Ax = Axf + buf * BM * ASX;
        int r0l = wm * 16 + g;
        int r1l = r0l + 8;
        int r0g = row0 + r0l, r1g = row0 + r1l;

        float acc[4][4];
        #pragma unroll
        for (int j = 0; j < 4; j++)
            #pragma unroll
            for (int q = 0; q < 4; q++) acc[j][q] = 0.f;

        int arow = wm * 16 + (lane & 15);
        int acol = (lane >> 4) * 8;
        int brow = (lane & 7) + ((lane >> 3) & 1) * 8;
        int bcol = wn * 32 + ((lane >> 4) & 1) * 8;

        // ---- agg half: ldmatrix A fragments (k in [0,128)) ----
        #pragma unroll
        for (int kk = 0; kk < D; kk += 16) {
            unsigned a0, a1, a2, a3;
            unsigned ad = (unsigned)__cvta_generic_to_shared(
                &Ab[(size_t)arow * ASB + kk + acol]);
            asm volatile(
                "ldmatrix.sync.aligned.m8n8.x4.shared.b16 {%0,%1,%2,%3}, [%4];"
                : "=r"(a0), "=r"(a1), "=r"(a2), "=r"(a3) : "r"(ad));
            #pragma unroll
            for (int nt = 0; nt < 2; nt++) {
                unsigned b0, b1, b2, b3;
                unsigned bd = (unsigned)__cvta_generic_to_shared(
                    &Bs[(size_t)(kk + brow) * BS + bcol + nt * 16]);
                asm volatile(
                    "ldmatrix.sync.aligned.m8n8.x4.trans.shared.b16 {%0,%1,%2,%3}, [%4];"
                    : "=r"(b0), "=r"(b1), "=r"(b2), "=r"(b3) : "r"(bd));
                asm volatile(
                    "mma.sync.aligned.m16n8k16.row.col.f32.bf16.bf16.f32 "
                    "{%0,%1,%2,%3}, {%4,%5,%6,%7}, {%8,%9}, {%0,%1,%2,%3};"
                    : "+f"(acc[nt*2][0]), "+f"(acc[nt*2][1]),
                      "+f"(acc[nt*2][2]), "+f"(acc[nt*2][3])
                    : "r"(a0), "r"(a1), "r"(a2), "r"(a3), "r"(b0), "r"(b1));
                asm volatile(
                    "mma.sync.aligned.m16n8k16.row.col.f32.bf16.bf16.f32 "
                    "{%0,%1,%2,%3}, {%4,%5,%6,%7}, {%8,%9}, {%0,%1,%2,%3};"
                    : "+f"(acc[nt*2+1][0]), "+f"(acc[nt*2+1][1]),
                      "+f"(acc[nt*2+1][2]), "+f"(acc[nt*2+1][3])
                    : "r"(a0), "r"(a1), "r"(a2), "r"(a3), "r"(b2), "r"(b3));
            }
        }

        // ---- x half: LDS.64+cvt fragments (k in [128,256)) ----
        #pragma unroll
        for (int kk = D; kk < 256; kk += 16) {
            int kx = kk - D;
            float2 f0 = *reinterpret_cast<const float2*>(&Ax[r0l * ASX + kx + tg2]);
            float2 f1 = *reinterpret_cast<const float2*>(&Ax[r1l * ASX + kx + tg2]);
            float2 f2 = *reinterpret_cast<const float2*>(&Ax[r0l * ASX + kx + 8 + tg2]);
            float2 f3 = *reinterpret_cast<const float2*>(&Ax[r1l * ASX + kx + 8 + tg2]);
            __nv_bfloat162 h0 = __floats2bfloat162_rn(f0.x, f0.y);
            __nv_bfloat162 h1 = __floats2bfloat162_rn(f1.x, f1.y);
            __nv_bfloat162 h2 = __floats2bfloat162_rn(f2.x, f2.y);
            __nv_bfloat162 h3 = __floats2bfloat162_rn(f3.x, f3.y);
            unsigned a0 = *reinterpret_cast<unsigned*>(&h0);
            unsigned a1 = *reinterpret_cast<unsigned*>(&h1);
            unsigned a2 = *reinterpret_cast<unsigned*>(&h2);
            unsigned a3 = *reinterpret_cast<unsigned*>(&h3);
            #pragma unroll
            for (int nt = 0; nt < 2; nt++) {
                unsigned b0, b1, b2, b3;
                unsigned bd = (unsigned)__cvta_generic_to_shared(
                    &Bs[(size_t)(kk + brow) * BS + bcol + nt * 16]);
                asm volatile(
                    "ldmatrix.sync.aligned.m8n8.x4.trans.shared.b16 {%0,%1,%2,%3}, [%4];"
                    : "=r"(b0), "=r"(b1), "=r"(b2), "=r"(b3) : "r"(bd));
                asm volatile(
                    "mma.sync.aligned.m16n8k16.row.col.f32.bf16.bf16.f32 "
                    "{%0,%1,%2,%3}, {%4,%5,%6,%7}, {%8,%9}, {%0,%1,%2,%3};"
                    : "+f"(acc[nt*2][0]), "+f"(acc[nt*2][1]),
                      "+f"(acc[nt*2][2]), "+f"(acc[nt*2][3])
                    : "r"(a0), "r"(a1), "r"(a2), "r"(a3), "r"(b0), "r"(b1));
                asm volatile(
                    "mma.sync.aligned.m16n8k16.row.col.f32.bf16.bf16.f32 "
                    "{%0,%1,%2,%3}, {%4,%5,%6,%7}, {%8,%9}, {%0,%1,%2,%3};"
                    : "+f"(acc[nt*2+1][0]), "+f"(acc[nt*2+1][1]),
                      "+f"(acc[nt*2+1][2]), "+f"(acc[nt*2+1][3])
                    : "r"(a0), "r"(a1), "r"(a2), "r"(a3), "r"(b2), "r"(b3));
            }
        }

        // ---- epilogue: out = x(smem fp32) + res * tanh(acc) ----
        #pragma unroll
        for (int j = 0; j < 4; j++) {
            int col = wn * 32 + j * 8 + tg2;
            if (r0g < Nn) {
                float2 xv = *reinterpret_cast<const float2*>(&Ax[r0l * ASX + col]);
                float2 o;
                o.x = xv.x + resv * tanh_approx(acc[j][0]);
                o.y = xv.y + resv * tanh_approx(acc[j][1]);
                *reinterpret_cast<float2*>(out + (size_t)r0g * D + col) = o;
            }
            if (r1g < Nn) {
                float2 xv = *reinterpret_cast<const float2*>(&Ax[r1l * ASX + col]);
                float2 o;
                o.x = xv.x + resv * tanh_approx(acc[j][2]);
                o.y = xv.y + resv * tanh_approx(acc[j][3]);
                *reinterpret_cast<float2*>(out + (size_t)r1g * D + col) = o;
            }
        }
        __syncthreads();
        buf ^= 1;
    }
}

// ---------------------------------------------------------------------------
extern "C" void kernel_launch(void* const* d_in, const int* in_sizes, int n_in,
                              void* d_out, int out_size)
{
    const float* emb    = (const float*)d_in[0];
    const float* change = (const float*)d_in[1];
    const float* W1     = (const float*)d_in[2];
    const float* Wl1    = (const float*)d_in[3];
    const float* rel1   = (const float*)d_in[4];
    const float* W2     = (const float*)d_in[5];
    const float* Wl2    = (const float*)d_in[6];
    const float* rel2   = (const float*)d_in[7];
    const float* res    = (const float*)d_in[8];
    const float* jw     = (const float*)d_in[9];
    const float* ewj    = (const float*)d_in[10];
    const int*   ei     = (const int*)d_in[11];
    const int*   et     = (const int*)d_in[12];
    const int*   ej     = (const int*)d_in[13];

    int Nn = in_sizes[0] / D;
    int E  = in_sizes[12];
    int EJ = in_sizes[10];
    int ntiles = (Nn + BM - 1) / BM;
    int nscan = (Nn + SCAN_B - 1) / SCAN_B;
    size_t rowBytes = (size_t)Nn * D * sizeof(float);

    float* out_change = (float*)d_out;
    float* out_dch    = (float*)d_out + (size_t)Nn * D;

    void *p_agg, *p_h, *p_cnt;
    cudaGetSymbolAddress(&p_agg, g_aggbf);
    cudaGetSymbolAddress(&p_h,   g_h);
    cudaGetSymbolAddress(&p_cnt, g_cnt);
    __nv_bfloat16* agg = (__nv_bfloat16*)p_agg;
    float* hbuf = (float*)p_h;

    cudaFuncSetAttribute(fused_gemm, cudaFuncAttributeMaxDynamicSharedMemorySize,
                         SMEM_BYTES);

    int convBlocks = (Nn + 7) / 8;

    // ---- CSR build (shared by both layers) ----
    cudaMemsetAsync(p_cnt, 0, (size_t)Nn * sizeof(int), 0);
    deg_count<<<(E + 255) / 256, 256>>>(ei, E);
    scan1<<<nscan, SCAN_B>>>(Nn);
    scan2<<<1, 32>>>(nscan);
    scan3<<<(Nn + 255) / 256, 256>>>(Nn);
    csr_fill<<<(E + 255) / 256, 256>>>(ei, et, E);

    // Layer 1
    conv_gather<<<convBlocks, 256>>>(emb, rel1, agg, Nn);
    fused_gemm<<<152, 512, SMEM_BYTES>>>(emb, W1, Wl1, res, agg, hbuf, Nn, ntiles);

    // Layer 2 (agg buffer reused; stays L2-resident)
    conv_gather<<<convBlocks, 256>>>(hbuf, rel2, agg, Nn);
    fused_gemm<<<152, 512, SMEM_BYTES>>>(hbuf, W2, Wl2, res, agg, out_dch, Nn, ntiles);

    // Jump diffusion accumulates directly onto dchange
    jump_scatter<<<2368, 256>>>(emb, ewj, jw, ej, out_dch, EJ);

    // change passthrough
    cudaMemcpyAsync(out_change, change, rowBytes, cudaMemcpyDeviceToDevice, 0);
}

// round 13
// speedup vs baseline: 2.3084x; 1.0244x over previous
#include <cuda_runtime.h>
#include <cuda_bf16.h>
#include <math.h>

#define D 128
#define NMAX 100000
#define EMAX 620000
#define SCAN_B 512

// Static scratch (no allocations allowed)
__device__ __nv_bfloat16 g_aggbf[(size_t)NMAX * D];   // 25.6 MB, both layers
__device__ float g_h[(size_t)NMAX * D];
__device__ int   g_cnt [NMAX];
__device__ int   g_ptr [NMAX];     // exclusive prefix; post-fill: ptr[i]=excl[i+1]
__device__ int   g_bsum[256];
__device__ int   g_boff[256];
__device__ unsigned g_ebuf[EMAX];  // src | (type<<17)

__device__ __forceinline__ void red_add_v4(float* p, float4 v) {
    asm volatile("red.global.add.v4.f32 [%0], {%1,%2,%3,%4};"
                 :: "l"(p), "f"(v.x), "f"(v.y), "f"(v.z), "f"(v.w) : "memory");
}

__device__ __forceinline__ float tanh_approx(float x) {
    float y;
    asm("tanh.approx.f32 %0, %1;" : "=f"(y) : "f"(x));
    return y;
}

__device__ __forceinline__ void cp16(unsigned saddr, const void* g, int srcsize) {
    asm volatile("cp.async.cg.shared.global [%0], [%1], 16, %2;"
                 :: "r"(saddr), "l"(g), "r"(srcsize));
}

// ---------------------------------------------------------------------------
// CSR build
// ---------------------------------------------------------------------------
__global__ void deg_count(const int* __restrict__ ei, int E) {
    int i = blockIdx.x * blockDim.x + threadIdx.x;
    if (i < E) atomicAdd(&g_cnt[__ldg(ei + E + i)], 1);
}

__global__ void scan1(int Nn) {
    __shared__ int warpsums[16];
    int i = blockIdx.x * SCAN_B + threadIdx.x;
    int lane = threadIdx.x & 31, w = threadIdx.x >> 5;
    int v = (i < Nn) ? g_cnt[i] : 0;
    int s = v;
    #pragma unroll
    for (int o = 1; o < 32; o <<= 1) {
        int t = __shfl_up_sync(~0u, s, o);
        if (lane >= o) s += t;
    }
    if (lane == 31) warpsums[w] = s;
    __syncthreads();
    if (w == 0) {
        int ws = (lane < 16) ? warpsums[lane] : 0;
        #pragma unroll
        for (int o = 1; o < 16; o <<= 1) {
            int t = __shfl_up_sync(~0u, ws, o);
            if (lane >= o) ws += t;
        }
        if (lane < 16) warpsums[lane] = ws;
    }
    __syncthreads();
    int base = (w > 0) ? warpsums[w - 1] : 0;
    if (i < Nn) g_ptr[i] = base + s - v;
    if (threadIdx.x == SCAN_B - 1) g_bsum[blockIdx.x] = base + s;
}

// Parallel block-scan over per-block sums (nb <= 256); one 256-thread block.
__global__ void scan2(int nb) {
    __shared__ int warpsums[8];
    int i = threadIdx.x;
    int lane = i & 31, w = i >> 5;
    int v = (i < nb) ? g_bsum[i] : 0;
    int s = v;
    #pragma unroll
    for (int o = 1; o < 32; o <<= 1) {
        int t = __shfl_up_sync(~0u, s, o);
        if (lane >= o) s += t;
    }
    if (lane == 31) warpsums[w] = s;
    __syncthreads();
    if (w == 0) {
        int ws = (lane < 8) ? warpsums[lane] : 0;
        #pragma unroll
        for (int o = 1; o < 8; o <<= 1) {
            int t = __shfl_up_sync(~0u, ws, o);
            if (lane >= o) ws += t;
        }
        if (lane < 8) warpsums[lane] = ws;
    }
    __syncthreads();
    int base = (w > 0) ? warpsums[w - 1] : 0;
    if (i < nb) g_boff[i] = base + s - v;   // exclusive prefix
}

__global__ void scan3(int Nn) {
    int i = blockIdx.x * blockDim.x + threadIdx.x;
    if (i < Nn) g_ptr[i] += g_boff[i / SCAN_B];
}

// Bumps g_ptr[dst] itself: afterwards ptr[i] == exclusive_prefix[i+1].
__global__ void csr_fill(const int* __restrict__ ei, const int* __restrict__ et, int E) {
    int e = blockIdx.x * blockDim.x + threadIdx.x;
    if (e < E) {
        int dst = __ldg(ei + E + e);
        int p = atomicAdd(&g_ptr[dst], 1);
        g_ebuf[p] = (unsigned)__ldg(ei + e) | ((unsigned)__ldg(et + e) << 17);
    }
}

// ---------------------------------------------------------------------------
// Gather conv: warp per destination; writes NORMALIZED agg in bf16.
// After csr_fill: beg = ptr[node-1] (0 for node 0), end = ptr[node].
// ---------------------------------------------------------------------------
__global__ __launch_bounds__(256)
void conv_gather(const float* __restrict__ x,
                 const float* __restrict__ rel,
                 __nv_bfloat16* __restrict__ agg,
                 int Nn)
{
    int node = blockIdx.x * (blockDim.x >> 5) + (threadIdx.x >> 5);
    if (node >= Nn) return;
    int lane = threadIdx.x & 31;
    int beg = (node == 0) ? 0 : __ldg(&g_ptr[node - 1]);
    int end = __ldg(&g_ptr[node]);
    float4 acc = make_float4(0.f, 0.f, 0.f, 0.f);
    for (int i = beg; i < end; i++) {
        unsigned e = __ldg(&g_ebuf[i]);
        int src = e & 0x1FFFF;
        int typ = e >> 17;
        float4 xv = reinterpret_cast<const float4*>(x   + (size_t)src * D)[lane];
        float4 rv = reinterpret_cast<const float4*>(rel + (size_t)typ * D)[lane];
        acc.x += xv.x * rv.x; acc.y += xv.y * rv.y;
        acc.z += xv.z * rv.z; acc.w += xv.w * rv.w;
    }
    float inv = 1.0f / fmaxf((float)(end - beg), 1.0f);
    __nv_bfloat162 p01 = __floats2bfloat162_rn(acc.x * inv, acc.y * inv);
    __nv_bfloat162 p23 = __floats2bfloat162_rn(acc.z * inv, acc.w * inv);
    unsigned u0 = *reinterpret_cast<unsigned*>(&p01);
    unsigned u1 = *reinterpret_cast<unsigned*>(&p23);
    reinterpret_cast<uint2*>(agg + (size_t)node * D)[lane] = make_uint2(u0, u1);
}

// ---------------------------------------------------------------------------
// Jump scatter: out[dst] += jw * ew[e] * emb[src]
// ---------------------------------------------------------------------------
__global__ __launch_bounds__(256)
void jump_scatter(const float* __restrict__ emb,
                  const float* __restrict__ ew,
                  const float* __restrict__ jwp,
                  const int* __restrict__ ej,
                  float* __restrict__ out, int EJ)
{
    float jw = __ldg(jwp);
    int lane = threadIdx.x & 31;
    int warp = blockIdx.x * (blockDim.x >> 5) + (threadIdx.x >> 5);
    int nwarps = gridDim.x * (blockDim.x >> 5);
    for (int e = warp; e < EJ; e += nwarps) {
        int src = __ldg(ej + e);
        int dst = __ldg(ej + EJ + e);
        float w = jw * __ldg(ew + e);
        float4 v = reinterpret_cast<const float4*>(emb + (size_t)src * D)[lane];
        v.x *= w; v.y *= w; v.z *= w; v.w *= w;
        red_add_v4(out + (size_t)dst * D + lane * 4, v);
    }
}

// ---------------------------------------------------------------------------
// Pipelined fused GEMM (TRIPLE-buffered, prefetch distance 2):
//   out = x + res * tanh( aggbf @ Wa + x @ Wx )
// A split: agg half staged bf16 via cp.async (ldmatrix fragments),
//          x half staged fp32 (LDS+cvt fragments; epilogue reads it fp32).
// 512 threads = 16 warps (4 m x 4 n), 1 CTA/SM, smem ~218KB.
// ---------------------------------------------------------------------------
#define BM 64
#define ASB 136                               // bf16 per agg row (272B, padded)
#define ASX 132                               // fp32 per x row (528B, padded)
#define BS  136
#define NBUF 3
#define ABF_BYTES (BM * ASB * 2)              // 17408 per buf
#define AXF_BYTES (BM * ASX * 4)              // 33792 per buf
#define SMEM_B_OFF (NBUF * (ABF_BYTES + AXF_BYTES))   // 153600
#define SMEM_BYTES (SMEM_B_OFF + 256 * BS * 2)        // 223232

__global__ __launch_bounds__(512, 1)
void fused_gemm(const float* __restrict__ x,
                const float* __restrict__ Wa,
                const float* __restrict__ Wx,
                const float* __restrict__ resp,
                const __nv_bfloat16* __restrict__ aggbf,
                float* __restrict__ out,
                int Nn, int ntiles)
{
    extern __shared__ char smraw[];
    __nv_bfloat16* Abf = reinterpret_cast<__nv_bfloat16*>(smraw);             // [3][BM*ASB]
    float* Axf = reinterpret_cast<float*>(smraw + NBUF * ABF_BYTES);          // [3][BM*ASX]
    __nv_bfloat16* Bs = reinterpret_cast<__nv_bfloat16*>(smraw + SMEM_B_OFF);

    int tid  = threadIdx.x;
    int lane = tid & 31;
    int wid  = tid >> 5;
    int wm   = wid & 3;
    int wn   = wid >> 2;
    int g    = lane >> 2;
    int tg2  = (lane & 3) * 2;

    unsigned sAbf = (unsigned)__cvta_generic_to_shared(Abf);
    unsigned sAxf = (unsigned)__cvta_generic_to_shared(Axf);

    // ---- stage weights once (bf16) ----
    for (int idx = tid; idx < 256 * D / 4; idx += 512) {
        int k  = idx >> 5;
        int c4 = (idx & 31) * 4;
        const float* src = (k < D) ? (Wa + (size_t)k * D) : (Wx + (size_t)(k - D) * D);
        float4 v = *reinterpret_cast<const float4*>(src + c4);
        *reinterpret_cast<__nv_bfloat162*>(&Bs[k * BS + c4])     = __floats2bfloat162_rn(v.x, v.y);
        *reinterpret_cast<__nv_bfloat162*>(&Bs[k * BS + c4 + 2]) = __floats2bfloat162_rn(v.z, v.w);
    }

    float resv = __ldg(resp);
    int stride = gridDim.x;

    // staging: 48 16B-chunks per row (16 agg-bf16 + 32 x-fp32), 64 rows
    auto stage = [&](int tile, int buf) {
        int row0 = tile * BM;
        unsigned b_bf = sAbf + (unsigned)buf * ABF_BYTES;
        unsigned b_xf = sAxf + (unsigned)buf * AXF_BYTES;
        for (int i = tid; i < BM * 48; i += 512) {
            int r = i / 48, c = i % 48;
            int row = row0 + r;
            int ok = (row < Nn) ? 16 : 0;
            if (c < 16) {
                cp16(b_bf + (unsigned)(r * ASB + c * 8) * 2,
                     aggbf + (size_t)row * D + c * 8, ok);
            } else {
                int cx = c - 16;
                cp16(b_xf + (unsigned)(r * ASX + cx * 4) * 4,
                     x + (size_t)row * D + cx * 4, ok);
            }
        }
        asm volatile("cp.async.commit_group;" ::: "memory");
    };

    int t0 = blockIdx.x;
    stage(t0, 0);
    if (t0 + stride < ntiles) stage(t0 + stride, 1);

    int buf = 0;
    for (int t = t0; t < ntiles; t += stride) {
        int row0 = t * BM;
        // prefetch distance 2, then wait with EXACT pending count for buf
        int t2 = t + 2 * stride;
        if (t2 < ntiles) {
            stage(t2, (buf + 2) % NBUF);
            asm volatile("cp.async.wait_group 2;" ::: "memory");
        } else if (t + stride < ntiles) {
            asm volatile("cp.async.wait_group 1;" ::: "memory");
        } else {
            asm volatile("cp.async.wait_group 0;" ::: "memory");
        }
        __syncthreads();

        const __nv_bfloat16* Ab = Abf + buf * BM * ASB;
        const float* Ax = Axf + buf * BM * ASX;
        int r0l = wm * 16 + g;
        int r1l = r0l + 8;
        int r0g = row0 + r0l, r1g = row0 + r1l;

        float acc[4][4];
        #pragma unroll
        for (int j = 0; j < 4; j++)
            #pragma unroll
            for (int q = 0; q < 4; q++) acc[j][q] = 0.f;

        int arow = wm * 16 + (lane & 15);
        int acol = (lane >> 4) * 8;
        int brow = (lane & 7) + ((lane >> 3) & 1) * 8;
        int bcol = wn * 32 + ((lane >> 4) & 1) * 8;

        // ---- agg half: ldmatrix A fragments (k in [0,128)) ----
        #pragma unroll
        for (int kk = 0; kk < D; kk += 16) {
            unsigned a0, a1, a2, a3;
            unsigned ad = (unsigned)__cvta_generic_to_shared(
                &Ab[(size_t)arow * ASB + kk + acol]);
            asm volatile(
                "ldmatrix.sync.aligned.m8n8.x4.shared.b16 {%0,%1,%2,%3}, [%4];"
                : "=r"(a0), "=r"(a1), "=r"(a2), "=r"(a3) : "r"(ad));
            #pragma unroll
            for (int nt = 0; nt < 2; nt++) {
                unsigned b0, b1, b2, b3;
                unsigned bd = (unsigned)__cvta_generic_to_shared(
                    &Bs[(size_t)(kk + brow) * BS + bcol + nt * 16]);
                asm volatile(
                    "ldmatrix.sync.aligned.m8n8.x4.trans.shared.b16 {%0,%1,%2,%3}, [%4];"
                    : "=r"(b0), "=r"(b1), "=r"(b2), "=r"(b3) : "r"(bd));
                asm volatile(
                    "mma.sync.aligned.m16n8k16.row.col.f32.bf16.bf16.f32 "
                    "{%0,%1,%2,%3}, {%4,%5,%6,%7}, {%8,%9}, {%0,%1,%2,%3};"
                    : "+f"(acc[nt*2][0]), "+f"(acc[nt*2][1]),
                      "+f"(acc[nt*2][2]), "+f"(acc[nt*2][3])
                    : "r"(a0), "r"(a1), "r"(a2), "r"(a3), "r"(b0), "r"(b1));
                asm volatile(
                    "mma.sync.aligned.m16n8k16.row.col.f32.bf16.bf16.f32 "
                    "{%0,%1,%2,%3}, {%4,%5,%6,%7}, {%8,%9}, {%0,%1,%2,%3};"
                    : "+f"(acc[nt*2+1][0]), "+f"(acc[nt*2+1][1]),
                      "+f"(acc[nt*2+1][2]), "+f"(acc[nt*2+1][3])
                    : "r"(a0), "r"(a1), "r"(a2), "r"(a3), "r"(b2), "r"(b3));
            }
        }

        // ---- x half: LDS.64+cvt fragments (k in [128,256)) ----
        #pragma unroll
        for (int kk = D; kk < 256; kk += 16) {
            int kx = kk - D;
            float2 f0 = *reinterpret_cast<const float2*>(&Ax[r0l * ASX + kx + tg2]);
            float2 f1 = *reinterpret_cast<const float2*>(&Ax[r1l * ASX + kx + tg2]);
            float2 f2 = *reinterpret_cast<const float2*>(&Ax[r0l * ASX + kx + 8 + tg2]);
            float2 f3 = *reinterpret_cast<const float2*>(&Ax[r1l * ASX + kx + 8 + tg2]);
            __nv_bfloat162 h0 = __floats2bfloat162_rn(f0.x, f0.y);
            __nv_bfloat162 h1 = __floats2bfloat162_rn(f1.x, f1.y);
            __nv_bfloat162 h2 = __floats2bfloat162_rn(f2.x, f2.y);
            __nv_bfloat162 h3 = __floats2bfloat162_rn(f3.x, f3.y);
            unsigned a0 = *reinterpret_cast<unsigned*>(&h0);
            unsigned a1 = *reinterpret_cast<unsigned*>(&h1);
            unsigned a2 = *reinterpret_cast<unsigned*>(&h2);
            unsigned a3 = *reinterpret_cast<unsigned*>(&h3);
            #pragma unroll
            for (int nt = 0; nt < 2; nt++) {
                unsigned b0, b1, b2, b3;
                unsigned bd = (unsigned)__cvta_generic_to_shared(
                    &Bs[(size_t)(kk + brow) * BS + bcol + nt * 16]);
                asm volatile(
                    "ldmatrix.sync.aligned.m8n8.x4.trans.shared.b16 {%0,%1,%2,%3}, [%4];"
                    : "=r"(b0), "=r"(b1), "=r"(b2), "=r"(b3) : "r"(bd));
                asm volatile(
                    "mma.sync.aligned.m16n8k16.row.col.f32.bf16.bf16.f32 "
                    "{%0,%1,%2,%3}, {%4,%5,%6,%7}, {%8,%9}, {%0,%1,%2,%3};"
                    : "+f"(acc[nt*2][0]), "+f"(acc[nt*2][1]),
                      "+f"(acc[nt*2][2]), "+f"(acc[nt*2][3])
                    : "r"(a0), "r"(a1), "r"(a2), "r"(a3), "r"(b0), "r"(b1));
                asm volatile(
                    "mma.sync.aligned.m16n8k16.row.col.f32.bf16.bf16.f32 "
                    "{%0,%1,%2,%3}, {%4,%5,%6,%7}, {%8,%9}, {%0,%1,%2,%3};"
                    : "+f"(acc[nt*2+1][0]), "+f"(acc[nt*2+1][1]),
                      "+f"(acc[nt*2+1][2]), "+f"(acc[nt*2+1][3])
                    : "r"(a0), "r"(a1), "r"(a2), "r"(a3), "r"(b2), "r"(b3));
            }
        }

        // ---- epilogue: out = x(smem fp32) + res * tanh(acc) ----
        #pragma unroll
        for (int j = 0; j < 4; j++) {
            int col = wn * 32 + j * 8 + tg2;
            if (r0g < Nn) {
                float2 xv = *reinterpret_cast<const float2*>(&Ax[r0l * ASX + col]);
                float2 o;
                o.x = xv.x + resv * tanh_approx(acc[j][0]);
                o.y = xv.y + resv * tanh_approx(acc[j][1]);
                *reinterpret_cast<float2*>(out + (size_t)r0g * D + col) = o;
            }
            if (r1g < Nn) {
                float2 xv = *reinterpret_cast<const float2*>(&Ax[r1l * ASX + col]);
                float2 o;
                o.x = xv.x + resv * tanh_approx(acc[j][2]);
                o.y = xv.y + resv * tanh_approx(acc[j][3]);
                *reinterpret_cast<float2*>(out + (size_t)r1g * D + col) = o;
            }
        }
        __syncthreads();   // reads of buf complete before iter i+1 stages into it
        buf = (buf + 1) % NBUF;
    }
}

// ---------------------------------------------------------------------------
extern "C" void kernel_launch(void* const* d_in, const int* in_sizes, int n_in,
                              void* d_out, int out_size)
{
    const float* emb    = (const float*)d_in[0];
    const float* change = (const float*)d_in[1];
    const float* W1     = (const float*)d_in[2];
    const float* Wl1    = (const float*)d_in[3];
    const float* rel1   = (const float*)d_in[4];
    const float* W2     = (const float*)d_in[5];
    const float* Wl2    = (const float*)d_in[6];
    const float* rel2   = (const float*)d_in[7];
    const float* res    = (const float*)d_in[8];
    const float* jw     = (const float*)d_in[9];
    const float* ewj    = (const float*)d_in[10];
    const int*   ei     = (const int*)d_in[11];
    const int*   et     = (const int*)d_in[12];
    const int*   ej     = (const int*)d_in[13];

    int Nn = in_sizes[0] / D;
    int E  = in_sizes[12];
    int EJ = in_sizes[10];
    int ntiles = (Nn + BM - 1) / BM;
    int nscan = (Nn + SCAN_B - 1) / SCAN_B;
    size_t rowBytes = (size_t)Nn * D * sizeof(float);

    float* out_change = (float*)d_out;
    float* out_dch    = (float*)d_out + (size_t)Nn * D;

    void *p_agg, *p_h, *p_cnt;
    cudaGetSymbolAddress(&p_agg, g_aggbf);
    cudaGetSymbolAddress(&p_h,   g_h);
    cudaGetSymbolAddress(&p_cnt, g_cnt);
    __nv_bfloat16* agg = (__nv_bfloat16*)p_agg;
    float* hbuf = (float*)p_h;

    cudaFuncSetAttribute(fused_gemm, cudaFuncAttributeMaxDynamicSharedMemorySize,
                         SMEM_BYTES);

    int convBlocks = (Nn + 7) / 8;

    // Strictly serial stream 0 — identical capture structure to passing R11.
    // ---- CSR build (shared by both layers) ----
    cudaMemsetAsync(p_cnt, 0, (size_t)Nn * sizeof(int), 0);
    deg_count<<<(E + 255) / 256, 256>>>(ei, E);
    scan1<<<nscan, SCAN_B>>>(Nn);
    scan2<<<1, 256>>>(nscan);
    scan3<<<(Nn + 255) / 256, 256>>>(Nn);
    csr_fill<<<(E + 255) / 256, 256>>>(ei, et, E);

    // Layer 1
    conv_gather<<<convBlocks, 256>>>(emb, rel1, agg, Nn);
    fused_gemm<<<152, 512, SMEM_BYTES>>>(emb, W1, Wl1, res, agg, hbuf, Nn, ntiles);

    // Layer 2 (agg buffer reused; stays L2-resident)
    conv_gather<<<convBlocks, 256>>>(hbuf, rel2, agg, Nn);
    fused_gemm<<<152, 512, SMEM_BYTES>>>(hbuf, W2, Wl2, res, agg, out_dch, Nn, ntiles);

    // Jump diffusion accumulates directly onto dchange
    jump_scatter<<<2368, 256>>>(emb, ewj, jw, ej, out_dch, EJ);

    // change passthrough
    cudaMemcpyAsync(out_change, change, rowBytes, cudaMemcpyDeviceToDevice, 0);
}